// round 4
// baseline (speedup 1.0000x reference)
#include <cuda_runtime.h>
#include <cuda_fp16.h>
#include <cstdint>
#include <math.h>

// ---------------- problem constants ----------------
#define N_NODES   50000
#define N_EDGES0  800000
#define N_EDGES   850000      // + self loops
#define F_IN      128
#define HID       64
#define HEADS     4
#define C1        256         // HEADS*HID
#define NG        64
#define SLOPE     0.2f

// ---------------- scratch (device globals) ----------------
__device__ __align__(16) __half g_h1h[(size_t)N_NODES * C1];   // x @ W1 (fp16)
__device__ __align__(16) float  g_o1[(size_t)N_NODES * C1];    // layer-1 out (fp32)
__device__ __align__(16) __half g_h2h[(size_t)N_NODES * HID];  // o1 @ W2 (fp16)
__device__ __align__(16) float  g_o2[(size_t)N_NODES * HID];   // layer-2 out

__device__ float g_ssrc1[N_NODES * HEADS];
__device__ float g_sdst1[N_NODES * HEADS];
__device__ float g_ssrc2[N_NODES];
__device__ float g_sdst2[N_NODES];

__device__ int g_deg[N_NODES];
__device__ int g_cursor[N_NODES];
__device__ int g_rowptr[N_NODES + 1];
__device__ int g_esrc[N_EDGES];
__device__ int g_goff[NG + 1];

// ---------------- CSR build ----------------
__global__ void zero_kernel() {
    int stride = gridDim.x * blockDim.x;
    for (int i = blockIdx.x * blockDim.x + threadIdx.x; i < N_NODES; i += stride) {
        g_deg[i] = 0;
        g_cursor[i] = 0;
    }
}

__global__ void hist_kernel(const int* __restrict__ ei) {
    int e = blockIdx.x * blockDim.x + threadIdx.x;
    if (e >= N_EDGES) return;
    int dst = (e < N_EDGES0) ? ei[N_EDGES0 + e] : (e - N_EDGES0);
    atomicAdd(&g_deg[dst], 1);
}

__global__ void scan_kernel() {
    __shared__ int warpsums[32];
    __shared__ int s_carry;
    int t = threadIdx.x;
    int lane = t & 31, warp = t >> 5;
    if (t == 0) s_carry = 0;
    __syncthreads();
    for (int base = 0; base < N_NODES; base += 4096) {
        int i0 = base + t * 4;
        int v[4];
        #pragma unroll
        for (int j = 0; j < 4; j++) v[j] = (i0 + j < N_NODES) ? g_deg[i0 + j] : 0;
        int s = v[0] + v[1] + v[2] + v[3];
        int x = s;
        #pragma unroll
        for (int o = 1; o < 32; o <<= 1) {
            int y = __shfl_up_sync(0xffffffffu, x, o);
            if (lane >= o) x += y;
        }
        if (lane == 31) warpsums[warp] = x;
        __syncthreads();
        if (warp == 0) {
            int w = warpsums[lane];
            #pragma unroll
            for (int o = 1; o < 32; o <<= 1) {
                int y = __shfl_up_sync(0xffffffffu, w, o);
                if (lane >= o) w += y;
            }
            warpsums[lane] = w;
        }
        __syncthreads();
        int excl = x - s + (warp ? warpsums[warp - 1] : 0) + s_carry;
        int run = excl;
        #pragma unroll
        for (int j = 0; j < 4; j++) {
            if (i0 + j < N_NODES) g_rowptr[i0 + j] = run;
            run += v[j];
        }
        int total = warpsums[31];
        __syncthreads();
        if (t == 0) s_carry += total;
        __syncthreads();
    }
    if (t == 0) g_rowptr[N_NODES] = s_carry;
}

__global__ void scatter_kernel(const int* __restrict__ ei) {
    int e = blockIdx.x * blockDim.x + threadIdx.x;
    if (e >= N_EDGES) return;
    int src, dst;
    if (e < N_EDGES0) { src = ei[e]; dst = ei[N_EDGES0 + e]; }
    else { src = e - N_EDGES0; dst = src; }
    int pos = g_rowptr[dst] + atomicAdd(&g_cursor[dst], 1);
    g_esrc[pos] = src;
}

// ---------------- 3xTF32 tensor-core GEMM ----------------
// C_fp16[M,Nn] = A_fp32[M,K] @ B_fp32[K,Nn], ~fp32 accuracy via hi/lo split.
// Block tile 128x64, 4 warps (2x2), warp tile 64x32, k-tile 32.
// Fragments pre-split + stored fragment-contiguous in smem (conflict-free LDS).
#define MBM 128
#define MBN 64
#define MBK 32

__device__ __forceinline__ unsigned int cvt_tf32(float f) {
    unsigned int r; asm("cvt.rna.tf32.f32 %0, %1;" : "=r"(r) : "f"(f)); return r;
}

__device__ __forceinline__ void mma_tf32(float* d, const uint4& a, const uint2& b) {
    asm volatile(
        "mma.sync.aligned.m16n8k8.row.col.f32.tf32.tf32.f32 "
        "{%0,%1,%2,%3}, {%4,%5,%6,%7}, {%8,%9}, {%0,%1,%2,%3};"
        : "+f"(d[0]), "+f"(d[1]), "+f"(d[2]), "+f"(d[3])
        : "r"(a.x), "r"(a.y), "r"(a.z), "r"(a.w), "r"(b.x), "r"(b.y));
}

__global__ void __launch_bounds__(128) gemm_tf32_kernel(
    const float* __restrict__ A, const float* __restrict__ B, __half* __restrict__ C,
    int M, int Nn, int K)
{
    // fragment-contiguous: As[k8(4)][mt(8)][lane(32)][reg(4)], Bs[k8(4)][nt(8)][lane(32)][reg(2)]
    __shared__ float As_hi[4 * 8 * 32 * 4];
    __shared__ float As_lo[4 * 8 * 32 * 4];
    __shared__ float Bs_hi[4 * 8 * 32 * 2];
    __shared__ float Bs_lo[4 * 8 * 32 * 2];

    int t = threadIdx.x;
    int lane = t & 31, w = t >> 5;
    int wr = w >> 1, wc = w & 1;
    int bm = blockIdx.y * MBM, bn = blockIdx.x * MBN;

    float acc[4][4][4] = {};   // [mt][nt][reg]

    for (int kk = 0; kk < K; kk += MBK) {
        // ---- stage A: thread t owns row bm+t ----
        {
            int gm = bm + t;
            const float* arow = A + (size_t)gm * K + kk;
            int mt = t >> 4, r = t & 15;
            int rbit = (r >> 3) & 1;
            int lbase = (r & 7) << 2;
            #pragma unroll
            for (int q = 0; q < 8; q++) {
                float4 v = (gm < M) ? *(const float4*)(arow + q * 4)
                                    : make_float4(0.f, 0.f, 0.f, 0.f);
                float vv[4] = {v.x, v.y, v.z, v.w};
                #pragma unroll
                for (int j = 0; j < 4; j++) {
                    int kl = q * 4 + j;
                    int k8 = kl >> 3, kr = kl & 7;
                    int ln = lbase | (kr & 3);
                    int reg = rbit | ((kr >> 2) << 1);
                    int idx = (((k8 * 8 + mt) * 32) + ln) * 4 + reg;
                    float hf = __uint_as_float(cvt_tf32(vv[j]));
                    As_hi[idx] = hf;
                    As_lo[idx] = __uint_as_float(cvt_tf32(vv[j] - hf));
                }
            }
        }
        // ---- stage B: 2048 elems as 512 float4 ----
        {
            #pragma unroll
            for (int i = 0; i < 4; i++) {
                int vid = t + i * 128;
                int kl = vid >> 4;
                int n4 = (vid & 15) * 4;
                float4 v = *(const float4*)(B + (size_t)(kk + kl) * Nn + bn + n4);
                float vv[4] = {v.x, v.y, v.z, v.w};
                int k8 = kl >> 3, kr = kl & 7;
                int reg = (kr >> 2) & 1;
                #pragma unroll
                for (int j = 0; j < 4; j++) {
                    int nl = n4 + j;
                    int nt = nl >> 3, c = nl & 7;
                    int ln = (c << 2) | (kr & 3);
                    int idx = (((k8 * 8 + nt) * 32) + ln) * 2 + reg;
                    float hf = __uint_as_float(cvt_tf32(vv[j]));
                    Bs_hi[idx] = hf;
                    Bs_lo[idx] = __uint_as_float(cvt_tf32(vv[j] - hf));
                }
            }
        }
        __syncthreads();
        // ---- compute ----
        #pragma unroll
        for (int k8 = 0; k8 < 4; k8++) {
            uint4 ah[4], al[4];
            uint2 bh[4], bl[4];
            #pragma unroll
            for (int mt = 0; mt < 4; mt++) {
                int base = (((k8 * 8 + wr * 4 + mt) * 32) + lane) * 4;
                ah[mt] = *(const uint4*)&As_hi[base];
                al[mt] = *(const uint4*)&As_lo[base];
            }
            #pragma unroll
            for (int nt = 0; nt < 4; nt++) {
                int base = (((k8 * 8 + wc * 4 + nt) * 32) + lane) * 2;
                bh[nt] = *(const uint2*)&Bs_hi[base];
                bl[nt] = *(const uint2*)&Bs_lo[base];
            }
            #pragma unroll
            for (int mt = 0; mt < 4; mt++)
                #pragma unroll
                for (int nt = 0; nt < 4; nt++) {
                    mma_tf32(acc[mt][nt], ah[mt], bh[nt]);
                    mma_tf32(acc[mt][nt], ah[mt], bl[nt]);
                    mma_tf32(acc[mt][nt], al[mt], bh[nt]);
                }
        }
        __syncthreads();
    }
    // ---- epilogue: fp16 store ----
    int g = lane >> 2, tig = lane & 3;
    #pragma unroll
    for (int mt = 0; mt < 4; mt++) {
        int r0 = bm + wr * 64 + mt * 16 + g;
        int r1 = r0 + 8;
        #pragma unroll
        for (int nt = 0; nt < 4; nt++) {
            int c0 = bn + wc * 32 + nt * 8 + 2 * tig;
            if (r0 < M)
                *(__half2*)(C + (size_t)r0 * Nn + c0) =
                    __floats2half2_rn(acc[mt][nt][0], acc[mt][nt][1]);
            if (r1 < M)
                *(__half2*)(C + (size_t)r1 * Nn + c0) =
                    __floats2half2_rn(acc[mt][nt][2], acc[mt][nt][3]);
        }
    }
}

// ---------------- attention scores (warp per node[-head], fp16 h) ----------------
__global__ void scores1_kernel(const float* __restrict__ asrc, const float* __restrict__ adst) {
    int gw = (blockIdx.x * blockDim.x + threadIdx.x) >> 5;
    int lane = threadIdx.x & 31;
    if (gw >= N_NODES * HEADS) return;
    int n = gw >> 2, h = gw & 3;
    const __half* hp = g_h1h + (size_t)n * C1 + h * HID;
    float v0 = __half2float(hp[lane]), v1 = __half2float(hp[lane + 32]);
    float s1 = v0 * asrc[h * HID + lane] + v1 * asrc[h * HID + lane + 32];
    float s2 = v0 * adst[h * HID + lane] + v1 * adst[h * HID + lane + 32];
    #pragma unroll
    for (int o = 16; o; o >>= 1) {
        s1 += __shfl_down_sync(0xffffffffu, s1, o);
        s2 += __shfl_down_sync(0xffffffffu, s2, o);
    }
    if (lane == 0) {
        g_ssrc1[n * 4 + h] = s1;
        g_sdst1[n * 4 + h] = s2;
    }
}

__global__ void scores2_kernel(const float* __restrict__ asrc, const float* __restrict__ adst) {
    int gw = (blockIdx.x * blockDim.x + threadIdx.x) >> 5;
    int lane = threadIdx.x & 31;
    if (gw >= N_NODES) return;
    const __half* hp = g_h2h + (size_t)gw * HID;
    float v0 = __half2float(hp[lane]), v1 = __half2float(hp[lane + 32]);
    float s1 = v0 * asrc[lane] + v1 * asrc[lane + 32];
    float s2 = v0 * adst[lane] + v1 * adst[lane + 32];
    #pragma unroll
    for (int o = 16; o; o >>= 1) {
        s1 += __shfl_down_sync(0xffffffffu, s1, o);
        s2 += __shfl_down_sync(0xffffffffu, s2, o);
    }
    if (lane == 0) {
        g_ssrc2[gw] = s1;
        g_sdst2[gw] = s2;
    }
}

// ---------------- aggregation layer 1 (fp16 gather) ----------------
// block 256 = 4 edge-groups x 64 lanes; lane covers 4 channels (8B fp16 load).
// softmax without max-subtraction (shift-invariant; logits O(10), fp32-safe).
#define CH1 64
__global__ void __launch_bounds__(256) aggregate1_kernel(const float* __restrict__ b1) {
    int n = blockIdx.x;
    int t = threadIdx.x;
    int g = t >> 6, l = t & 63;
    int h = l >> 4;
    int r0 = g_rowptr[n], r1 = g_rowptr[n + 1];

    __shared__ float wsh[CH1][HEADS];
    __shared__ int   ssh[CH1];
    __shared__ float4 sacc[256];
    __shared__ float sden[4][HEADS];
    __shared__ float sdsh[HEADS];
    if (t < HEADS) sdsh[t] = g_sdst1[n * 4 + t];

    float4 acc = make_float4(0.f, 0.f, 0.f, 0.f);
    float den = 0.f;

    for (int base = r0; base < r1; base += CH1) {
        int cnt = min(CH1, r1 - base);
        __syncthreads();
        for (int idx = t; idx < cnt * 4; idx += 256) {
            int e = idx >> 2, hh = idx & 3;
            int src = g_esrc[base + e];
            if (hh == 0) ssh[e] = src;
            float s = g_ssrc1[src * 4 + hh] + sdsh[hh];
            s = s > 0.f ? s : SLOPE * s;
            wsh[e][hh] = __expf(s);
        }
        __syncthreads();
        for (int e = g; e < cnt; e += 4) {
            float w = wsh[e][h];
            den += w;
            uint2 u = *(const uint2*)(g_h1h + (size_t)ssh[e] * C1 + l * 4);
            float2 f0 = __half22float2(*(__half2*)&u.x);
            float2 f1 = __half22float2(*(__half2*)&u.y);
            acc.x += w * f0.x; acc.y += w * f0.y;
            acc.z += w * f1.x; acc.w += w * f1.y;
        }
    }
    sacc[t] = acc;
    if ((l & 15) == 0) sden[g][h] = den;
    __syncthreads();
    if (t < 64) {
        float4 a0 = sacc[l], a1 = sacc[64 + l], a2 = sacc[128 + l], a3 = sacc[192 + l];
        float d = sden[0][h] + sden[1][h] + sden[2][h] + sden[3][h] + 1e-16f;
        float inv = 1.f / d;
        float4 bb = ((const float4*)b1)[l];
        float4 o;
        o.x = (a0.x + a1.x + a2.x + a3.x) * inv + bb.x;
        o.y = (a0.y + a1.y + a2.y + a3.y) * inv + bb.y;
        o.z = (a0.z + a1.z + a2.z + a3.z) * inv + bb.z;
        o.w = (a0.w + a1.w + a2.w + a3.w) * inv + bb.w;
        o.x = o.x > 0.f ? o.x : expm1f(o.x);
        o.y = o.y > 0.f ? o.y : expm1f(o.y);
        o.z = o.z > 0.f ? o.z : expm1f(o.z);
        o.w = o.w > 0.f ? o.w : expm1f(o.w);
        ((float4*)(g_o1 + (size_t)n * C1))[l] = o;
    }
}

// ---------------- aggregation layer 2 (fp16 gather) ----------------
#define CH2 64
__global__ void __launch_bounds__(128) aggregate2_kernel(const float* __restrict__ b2) {
    int n = blockIdx.x;
    int t = threadIdx.x;
    int g = t >> 4, l = t & 15;
    int r0 = g_rowptr[n], r1 = g_rowptr[n + 1];

    __shared__ float wsh[CH2];
    __shared__ int   ssh[CH2];
    __shared__ float4 sacc[128];
    __shared__ float sden[8];

    float sd = g_sdst2[n];
    float4 acc = make_float4(0.f, 0.f, 0.f, 0.f);
    float den = 0.f;

    for (int base = r0; base < r1; base += CH2) {
        int cnt = min(CH2, r1 - base);
        __syncthreads();
        if (t < cnt) {
            int src = g_esrc[base + t];
            ssh[t] = src;
            float s = g_ssrc2[src] + sd;
            s = s > 0.f ? s : SLOPE * s;
            wsh[t] = __expf(s);
        }
        __syncthreads();
        for (int e = g; e < cnt; e += 8) {
            float w = wsh[e];
            den += w;
            uint2 u = *(const uint2*)(g_h2h + (size_t)ssh[e] * HID + l * 4);
            float2 f0 = __half22float2(*(__half2*)&u.x);
            float2 f1 = __half22float2(*(__half2*)&u.y);
            acc.x += w * f0.x; acc.y += w * f0.y;
            acc.z += w * f1.x; acc.w += w * f1.y;
        }
    }
    sacc[t] = acc;
    if (l == 0) sden[g] = den;
    __syncthreads();
    if (t < 16) {
        float4 a = make_float4(0.f, 0.f, 0.f, 0.f);
        float d = 1e-16f;
        #pragma unroll
        for (int gg = 0; gg < 8; gg++) {
            float4 v = sacc[gg * 16 + l];
            a.x += v.x; a.y += v.y; a.z += v.z; a.w += v.w;
            d += sden[gg];
        }
        float inv = 1.f / d;
        float4 bb = ((const float4*)b2)[l];
        float4 o;
        o.x = a.x * inv + bb.x; o.y = a.y * inv + bb.y;
        o.z = a.z * inv + bb.z; o.w = a.w * inv + bb.w;
        o.x = o.x > 0.f ? o.x : expm1f(o.x);
        o.y = o.y > 0.f ? o.y : expm1f(o.y);
        o.z = o.z > 0.f ? o.z : expm1f(o.z);
        o.w = o.w > 0.f ? o.w : expm1f(o.w);
        ((float4*)(g_o2 + (size_t)n * HID))[l] = o;
    }
}

// ---------------- graph offsets ----------------
__global__ void graph_offsets_kernel(const int* __restrict__ batch) {
    int g = blockIdx.x * blockDim.x + threadIdx.x;
    if (g > NG) return;
    if (g == NG) { g_goff[NG] = N_NODES; return; }
    int lo = 0, hi = N_NODES;
    while (lo < hi) {
        int mid = (lo + hi) >> 1;
        if (batch[mid] < g) lo = mid + 1; else hi = mid;
    }
    g_goff[g] = lo;
}

// ---------------- pool + fc + log_softmax ----------------
__global__ void __launch_bounds__(256) pool_fc_kernel(const float* __restrict__ fcw,
                                                      const float* __restrict__ fcb,
                                                      float* __restrict__ out) {
    int g = blockIdx.x;
    int t = threadIdx.x;
    int c = t & 63, rep = t >> 6;
    int s = g_goff[g], e = g_goff[g + 1];
    float sum = 0.f;
    for (int i = s + rep; i < e; i += 4)
        sum += g_o2[(size_t)i * HID + c];
    __shared__ float red[256];
    red[t] = sum;
    __syncthreads();
    if (t < 64) {
        float tot = red[t] + red[t + 64] + red[t + 128] + red[t + 192];
        float cnt = (float)max(e - s, 1);
        float pooled = tot / cnt;
        red[t]      = pooled * fcw[c * 2 + 0];
        red[t + 64] = pooled * fcw[c * 2 + 1];
    }
    __syncthreads();
    if (t < 2) {
        float l = fcb[t];
        for (int i = 0; i < 64; i++) l += red[t * 64 + i];
        red[128 + t] = l;
    }
    __syncthreads();
    if (t == 0) {
        float l0 = red[128], l1 = red[129];
        float m = fmaxf(l0, l1);
        float lse = m + logf(__expf(l0 - m) + __expf(l1 - m));
        out[g * 2 + 0] = l0 - lse;
        out[g * 2 + 1] = l1 - lse;
    }
}

// ---------------- launch ----------------
extern "C" void kernel_launch(void* const* d_in, const int* in_sizes, int n_in,
                              void* d_out, int out_size) {
    const float* x    = (const float*)d_in[0];
    const int*   ei   = (const int*)d_in[1];
    const int*   bat  = (const int*)d_in[2];
    const float* W1   = (const float*)d_in[3];
    const float* as1  = (const float*)d_in[4];
    const float* ad1  = (const float*)d_in[5];
    const float* b1   = (const float*)d_in[6];
    const float* W2   = (const float*)d_in[7];
    const float* as2  = (const float*)d_in[8];
    const float* ad2  = (const float*)d_in[9];
    const float* b2   = (const float*)d_in[10];
    const float* fcw  = (const float*)d_in[11];
    const float* fcb  = (const float*)d_in[12];
    float* out = (float*)d_out;

    __half* h1p; cudaGetSymbolAddress((void**)&h1p, g_h1h);
    float*  o1p; cudaGetSymbolAddress((void**)&o1p, g_o1);
    __half* h2p; cudaGetSymbolAddress((void**)&h2p, g_h2h);

    zero_kernel<<<128, 256>>>();                                   // 0
    hist_kernel<<<(N_EDGES + 255) / 256, 256>>>(ei);               // 1
    scan_kernel<<<1, 1024>>>();                                    // 2

    dim3 g1(C1 / MBN, (N_NODES + MBM - 1) / MBM);
    gemm_tf32_kernel<<<g1, 128>>>(x, W1, h1p, N_NODES, C1, F_IN);  // 3

    scatter_kernel<<<(N_EDGES + 255) / 256, 256>>>(ei);            // 4
    scores1_kernel<<<(N_NODES * HEADS * 32 + 255) / 256, 256>>>(as1, ad1); // 5
    aggregate1_kernel<<<N_NODES, 256>>>(b1);                       // 6

    dim3 g2(HID / MBN, (N_NODES + MBM - 1) / MBM);
    gemm_tf32_kernel<<<g2, 128>>>(o1p, W2, h2p, N_NODES, HID, C1); // 7
    scores2_kernel<<<(N_NODES * 32 + 255) / 256, 256>>>(as2, ad2); // 8
    aggregate2_kernel<<<N_NODES, 128>>>(b2);                       // 9

    graph_offsets_kernel<<<1, 128>>>(bat);                         // 10
    pool_fc_kernel<<<NG, 256>>>(fcw, fcb, out);                    // 11
}

// round 5
// speedup vs baseline: 1.6474x; 1.6474x over previous
#include <cuda_runtime.h>
#include <cuda_fp16.h>
#include <cstdint>
#include <math.h>

// ---------------- problem constants ----------------
#define N_NODES   50000
#define N_EDGES0  800000
#define N_EDGES   850000      // + self loops
#define F_IN      128
#define HID       64
#define HEADS     4
#define C1        256         // HEADS*HID
#define NG        64
#define SLOPE     0.2f

// ---------------- scratch (device globals) ----------------
__device__ __align__(16) __half g_xh[(size_t)N_NODES * F_IN];   // x (fp16)
__device__ __align__(16) __half g_W1h[F_IN * C1];
__device__ __align__(16) __half g_W2h[C1 * HID];
__device__ __align__(16) __half g_h1h[(size_t)N_NODES * C1];    // x @ W1 (fp16)
__device__ __align__(16) __half g_o1h[(size_t)N_NODES * C1];    // layer-1 out (fp16)
__device__ __align__(16) __half g_h2h[(size_t)N_NODES * HID];   // o1 @ W2 (fp16)
__device__ __align__(16) float  g_o2[(size_t)N_NODES * HID];    // layer-2 out (fp32)

__device__ float g_ssrc1[N_NODES * HEADS];
__device__ float g_sdst1[N_NODES * HEADS];
__device__ float g_ssrc2[N_NODES];
__device__ float g_sdst2[N_NODES];

__device__ int g_deg[N_NODES];
__device__ int g_cursor[N_NODES];
__device__ int g_rowptr[N_NODES + 1];
__device__ int g_esrc[N_EDGES];
__device__ int g_goff[NG + 1];

// ---------------- fp32 -> fp16 convert (n % 4 == 0) ----------------
__global__ void f2h_kernel(const float* __restrict__ in, __half* __restrict__ out, int n) {
    int i = (blockIdx.x * blockDim.x + threadIdx.x) * 4;
    if (i >= n) return;
    float4 v = *(const float4*)(in + i);
    __half2 a = __floats2half2_rn(v.x, v.y);
    __half2 b = __floats2half2_rn(v.z, v.w);
    uint2 u;
    u.x = *(unsigned int*)&a;
    u.y = *(unsigned int*)&b;
    *(uint2*)(out + i) = u;
}

// ---------------- CSR build ----------------
__global__ void zero_kernel() {
    int stride = gridDim.x * blockDim.x;
    for (int i = blockIdx.x * blockDim.x + threadIdx.x; i < N_NODES; i += stride) {
        g_deg[i] = 0;
        g_cursor[i] = 0;
    }
}

__global__ void hist_kernel(const int* __restrict__ ei) {
    int e = blockIdx.x * blockDim.x + threadIdx.x;
    if (e >= N_EDGES) return;
    int dst = (e < N_EDGES0) ? ei[N_EDGES0 + e] : (e - N_EDGES0);
    atomicAdd(&g_deg[dst], 1);
}

__global__ void scan_kernel() {
    __shared__ int warpsums[32];
    __shared__ int s_carry;
    int t = threadIdx.x;
    int lane = t & 31, warp = t >> 5;
    if (t == 0) s_carry = 0;
    __syncthreads();
    for (int base = 0; base < N_NODES; base += 4096) {
        int i0 = base + t * 4;
        int v[4];
        #pragma unroll
        for (int j = 0; j < 4; j++) v[j] = (i0 + j < N_NODES) ? g_deg[i0 + j] : 0;
        int s = v[0] + v[1] + v[2] + v[3];
        int x = s;
        #pragma unroll
        for (int o = 1; o < 32; o <<= 1) {
            int y = __shfl_up_sync(0xffffffffu, x, o);
            if (lane >= o) x += y;
        }
        if (lane == 31) warpsums[warp] = x;
        __syncthreads();
        if (warp == 0) {
            int w = warpsums[lane];
            #pragma unroll
            for (int o = 1; o < 32; o <<= 1) {
                int y = __shfl_up_sync(0xffffffffu, w, o);
                if (lane >= o) w += y;
            }
            warpsums[lane] = w;
        }
        __syncthreads();
        int excl = x - s + (warp ? warpsums[warp - 1] : 0) + s_carry;
        int run = excl;
        #pragma unroll
        for (int j = 0; j < 4; j++) {
            if (i0 + j < N_NODES) g_rowptr[i0 + j] = run;
            run += v[j];
        }
        int total = warpsums[31];
        __syncthreads();
        if (t == 0) s_carry += total;
        __syncthreads();
    }
    if (t == 0) g_rowptr[N_NODES] = s_carry;
}

__global__ void scatter_kernel(const int* __restrict__ ei) {
    int e = blockIdx.x * blockDim.x + threadIdx.x;
    if (e >= N_EDGES) return;
    int src, dst;
    if (e < N_EDGES0) { src = ei[e]; dst = ei[N_EDGES0 + e]; }
    else { src = e - N_EDGES0; dst = src; }
    int pos = g_rowptr[dst] + atomicAdd(&g_cursor[dst], 1);
    g_esrc[pos] = src;
}

// ---------------- fp16 HMMA GEMM ----------------
// C_fp16[M,Nn] = A_fp16[M,K] @ B_fp16[K,Nn], fp32 accumulate.
// Block 128x64, 8 warps (4x2), warp tile 32x32, k-tile 32.
// Staging: vectorized 16B copies; fragments via ldmatrix (padded, conflict-free).
#define ASTR 40   // half stride of As row (80B)
#define BSTR 72   // half stride of Bs row (144B)

__device__ __forceinline__ unsigned int smem_u32(const void* p) {
    return (unsigned int)__cvta_generic_to_shared(p);
}

__device__ __forceinline__ void ldsm_x4(unsigned int* r, unsigned int addr) {
    asm volatile("ldmatrix.sync.aligned.m8n8.x4.shared.b16 {%0,%1,%2,%3}, [%4];"
                 : "=r"(r[0]), "=r"(r[1]), "=r"(r[2]), "=r"(r[3]) : "r"(addr));
}

__device__ __forceinline__ void ldsm_x4_t(unsigned int* r, unsigned int addr) {
    asm volatile("ldmatrix.sync.aligned.m8n8.x4.trans.shared.b16 {%0,%1,%2,%3}, [%4];"
                 : "=r"(r[0]), "=r"(r[1]), "=r"(r[2]), "=r"(r[3]) : "r"(addr));
}

__device__ __forceinline__ void mma_f16(float* d, const unsigned int* a,
                                        unsigned int b0, unsigned int b1) {
    asm volatile(
        "mma.sync.aligned.m16n8k16.row.col.f32.f16.f16.f32 "
        "{%0,%1,%2,%3}, {%4,%5,%6,%7}, {%8,%9}, {%0,%1,%2,%3};"
        : "+f"(d[0]), "+f"(d[1]), "+f"(d[2]), "+f"(d[3])
        : "r"(a[0]), "r"(a[1]), "r"(a[2]), "r"(a[3]), "r"(b0), "r"(b1));
}

__global__ void __launch_bounds__(256) gemm_hmma_kernel(
    const __half* __restrict__ A, const __half* __restrict__ B, __half* __restrict__ C,
    int M, int Nn, int K)
{
    __shared__ __half As[128 * ASTR];
    __shared__ __half Bs[32 * BSTR];

    int t = threadIdx.x;
    int lane = t & 31, w = t >> 5;
    int wm = w >> 1, wn = w & 1;
    int bm = blockIdx.y * 128, bn = blockIdx.x * 64;

    float acc[2][4][4] = {};   // [mt][nt][reg]

    for (int kk = 0; kk < K; kk += 32) {
        // stage A: 128 rows x 32 halfs; thread -> (row = t>>1, 32B chunk = t&1)
        {
            int row = t >> 1, ch = t & 1;
            int gm = bm + row;
            uint4 v0 = make_uint4(0, 0, 0, 0), v1 = v0;
            if (gm < M) {
                const uint4* src = (const uint4*)(A + (size_t)gm * K + kk + ch * 16);
                v0 = src[0]; v1 = src[1];
            }
            *(uint4*)&As[row * ASTR + ch * 16] = v0;
            *(uint4*)&As[row * ASTR + ch * 16 + 8] = v1;
        }
        // stage B: 32 rows x 64 halfs; thread -> (row = t>>3, 16B chunk = t&7)
        {
            int row = t >> 3, ch = t & 7;
            uint4 v = *(const uint4*)(B + (size_t)(kk + row) * Nn + bn + ch * 8);
            *(uint4*)&Bs[row * BSTR + ch * 8] = v;
        }
        __syncthreads();
        #pragma unroll
        for (int ks = 0; ks < 2; ks++) {
            unsigned int a[2][4], b[2][4];
            #pragma unroll
            for (int mt = 0; mt < 2; mt++) {
                unsigned int addr = smem_u32(
                    &As[(wm * 32 + mt * 16 + (lane & 15)) * ASTR + ks * 16 + (lane >> 4) * 8]);
                ldsm_x4(a[mt], addr);
            }
            #pragma unroll
            for (int np = 0; np < 2; np++) {
                unsigned int addr = smem_u32(
                    &Bs[(ks * 16 + (lane & 15)) * BSTR + wn * 32 + np * 16 + (lane >> 4) * 8]);
                ldsm_x4_t(b[np], addr);
            }
            #pragma unroll
            for (int mt = 0; mt < 2; mt++)
                #pragma unroll
                for (int nt = 0; nt < 4; nt++)
                    mma_f16(acc[mt][nt], a[mt], b[nt >> 1][(nt & 1) * 2], b[nt >> 1][(nt & 1) * 2 + 1]);
        }
        __syncthreads();
    }
    // epilogue: fp16 stores
    #pragma unroll
    for (int mt = 0; mt < 2; mt++) {
        int r0 = bm + wm * 32 + mt * 16 + (lane >> 2);
        #pragma unroll
        for (int nt = 0; nt < 4; nt++) {
            int c0 = bn + wn * 32 + nt * 8 + (lane & 3) * 2;
            if (r0 < M)
                *(__half2*)(C + (size_t)r0 * Nn + c0) =
                    __floats2half2_rn(acc[mt][nt][0], acc[mt][nt][1]);
            if (r0 + 8 < M)
                *(__half2*)(C + (size_t)(r0 + 8) * Nn + c0) =
                    __floats2half2_rn(acc[mt][nt][2], acc[mt][nt][3]);
        }
    }
}

// ---------------- attention scores (warp per node[-head], fp16 h) ----------------
__global__ void scores1_kernel(const float* __restrict__ asrc, const float* __restrict__ adst) {
    int gw = (blockIdx.x * blockDim.x + threadIdx.x) >> 5;
    int lane = threadIdx.x & 31;
    if (gw >= N_NODES * HEADS) return;
    int n = gw >> 2, h = gw & 3;
    const __half* hp = g_h1h + (size_t)n * C1 + h * HID;
    float v0 = __half2float(hp[lane]), v1 = __half2float(hp[lane + 32]);
    float s1 = v0 * asrc[h * HID + lane] + v1 * asrc[h * HID + lane + 32];
    float s2 = v0 * adst[h * HID + lane] + v1 * adst[h * HID + lane + 32];
    #pragma unroll
    for (int o = 16; o; o >>= 1) {
        s1 += __shfl_down_sync(0xffffffffu, s1, o);
        s2 += __shfl_down_sync(0xffffffffu, s2, o);
    }
    if (lane == 0) {
        g_ssrc1[n * 4 + h] = s1;
        g_sdst1[n * 4 + h] = s2;
    }
}

__global__ void scores2_kernel(const float* __restrict__ asrc, const float* __restrict__ adst) {
    int gw = (blockIdx.x * blockDim.x + threadIdx.x) >> 5;
    int lane = threadIdx.x & 31;
    if (gw >= N_NODES) return;
    const __half* hp = g_h2h + (size_t)gw * HID;
    float v0 = __half2float(hp[lane]), v1 = __half2float(hp[lane + 32]);
    float s1 = v0 * asrc[lane] + v1 * asrc[lane + 32];
    float s2 = v0 * adst[lane] + v1 * adst[lane + 32];
    #pragma unroll
    for (int o = 16; o; o >>= 1) {
        s1 += __shfl_down_sync(0xffffffffu, s1, o);
        s2 += __shfl_down_sync(0xffffffffu, s2, o);
    }
    if (lane == 0) {
        g_ssrc2[gw] = s1;
        g_sdst2[gw] = s2;
    }
}

// ---------------- aggregation layer 1 (fp16 gather, fp16 out) ----------------
// block 256 = 4 edge-groups x 64 lanes; lane covers 4 channels (8B fp16 load).
#define CH1 64
__global__ void __launch_bounds__(256) aggregate1_kernel(const float* __restrict__ b1) {
    int n = blockIdx.x;
    int t = threadIdx.x;
    int g = t >> 6, l = t & 63;
    int h = l >> 4;
    int r0 = g_rowptr[n], r1 = g_rowptr[n + 1];

    __shared__ float wsh[CH1][HEADS];
    __shared__ int   ssh[CH1];
    __shared__ float4 sacc[256];
    __shared__ float sden[4][HEADS];
    __shared__ float sdsh[HEADS];
    if (t < HEADS) sdsh[t] = g_sdst1[n * 4 + t];

    float4 acc = make_float4(0.f, 0.f, 0.f, 0.f);
    float den = 0.f;

    for (int base = r0; base < r1; base += CH1) {
        int cnt = min(CH1, r1 - base);
        __syncthreads();
        for (int idx = t; idx < cnt * 4; idx += 256) {
            int e = idx >> 2, hh = idx & 3;
            int src = g_esrc[base + e];
            if (hh == 0) ssh[e] = src;
            float s = g_ssrc1[src * 4 + hh] + sdsh[hh];
            s = s > 0.f ? s : SLOPE * s;
            wsh[e][hh] = __expf(s);
        }
        __syncthreads();
        for (int e = g; e < cnt; e += 4) {
            float w = wsh[e][h];
            den += w;
            uint2 u = *(const uint2*)(g_h1h + (size_t)ssh[e] * C1 + l * 4);
            float2 f0 = __half22float2(*(__half2*)&u.x);
            float2 f1 = __half22float2(*(__half2*)&u.y);
            acc.x += w * f0.x; acc.y += w * f0.y;
            acc.z += w * f1.x; acc.w += w * f1.y;
        }
    }
    sacc[t] = acc;
    if ((l & 15) == 0) sden[g][h] = den;
    __syncthreads();
    if (t < 64) {
        float4 a0 = sacc[l], a1 = sacc[64 + l], a2 = sacc[128 + l], a3 = sacc[192 + l];
        float d = sden[0][h] + sden[1][h] + sden[2][h] + sden[3][h] + 1e-16f;
        float inv = 1.f / d;
        float4 bb = ((const float4*)b1)[l];
        float4 o;
        o.x = (a0.x + a1.x + a2.x + a3.x) * inv + bb.x;
        o.y = (a0.y + a1.y + a2.y + a3.y) * inv + bb.y;
        o.z = (a0.z + a1.z + a2.z + a3.z) * inv + bb.z;
        o.w = (a0.w + a1.w + a2.w + a3.w) * inv + bb.w;
        o.x = o.x > 0.f ? o.x : expm1f(o.x);
        o.y = o.y > 0.f ? o.y : expm1f(o.y);
        o.z = o.z > 0.f ? o.z : expm1f(o.z);
        o.w = o.w > 0.f ? o.w : expm1f(o.w);
        __half2 p0 = __floats2half2_rn(o.x, o.y);
        __half2 p1 = __floats2half2_rn(o.z, o.w);
        uint2 u;
        u.x = *(unsigned int*)&p0;
        u.y = *(unsigned int*)&p1;
        ((uint2*)(g_o1h + (size_t)n * C1))[l] = u;
    }
}

// ---------------- aggregation layer 2 (fp16 gather, fp32 out) ----------------
#define CH2 64
__global__ void __launch_bounds__(128) aggregate2_kernel(const float* __restrict__ b2) {
    int n = blockIdx.x;
    int t = threadIdx.x;
    int g = t >> 4, l = t & 15;
    int r0 = g_rowptr[n], r1 = g_rowptr[n + 1];

    __shared__ float wsh[CH2];
    __shared__ int   ssh[CH2];
    __shared__ float4 sacc[128];
    __shared__ float sden[8];

    float sd = g_sdst2[n];
    float4 acc = make_float4(0.f, 0.f, 0.f, 0.f);
    float den = 0.f;

    for (int base = r0; base < r1; base += CH2) {
        int cnt = min(CH2, r1 - base);
        __syncthreads();
        if (t < cnt) {
            int src = g_esrc[base + t];
            ssh[t] = src;
            float s = g_ssrc2[src] + sd;
            s = s > 0.f ? s : SLOPE * s;
            wsh[t] = __expf(s);
        }
        __syncthreads();
        for (int e = g; e < cnt; e += 8) {
            float w = wsh[e];
            den += w;
            uint2 u = *(const uint2*)(g_h2h + (size_t)ssh[e] * HID + l * 4);
            float2 f0 = __half22float2(*(__half2*)&u.x);
            float2 f1 = __half22float2(*(__half2*)&u.y);
            acc.x += w * f0.x; acc.y += w * f0.y;
            acc.z += w * f1.x; acc.w += w * f1.y;
        }
    }
    sacc[t] = acc;
    if (l == 0) sden[g] = den;
    __syncthreads();
    if (t < 16) {
        float4 a = make_float4(0.f, 0.f, 0.f, 0.f);
        float d = 1e-16f;
        #pragma unroll
        for (int gg = 0; gg < 8; gg++) {
            float4 v = sacc[gg * 16 + l];
            a.x += v.x; a.y += v.y; a.z += v.z; a.w += v.w;
            d += sden[gg];
        }
        float inv = 1.f / d;
        float4 bb = ((const float4*)b2)[l];
        float4 o;
        o.x = a.x * inv + bb.x; o.y = a.y * inv + bb.y;
        o.z = a.z * inv + bb.z; o.w = a.w * inv + bb.w;
        o.x = o.x > 0.f ? o.x : expm1f(o.x);
        o.y = o.y > 0.f ? o.y : expm1f(o.y);
        o.z = o.z > 0.f ? o.z : expm1f(o.z);
        o.w = o.w > 0.f ? o.w : expm1f(o.w);
        ((float4*)(g_o2 + (size_t)n * HID))[l] = o;
    }
}

// ---------------- graph offsets ----------------
__global__ void graph_offsets_kernel(const int* __restrict__ batch) {
    int g = blockIdx.x * blockDim.x + threadIdx.x;
    if (g > NG) return;
    if (g == NG) { g_goff[NG] = N_NODES; return; }
    int lo = 0, hi = N_NODES;
    while (lo < hi) {
        int mid = (lo + hi) >> 1;
        if (batch[mid] < g) lo = mid + 1; else hi = mid;
    }
    g_goff[g] = lo;
}

// ---------------- pool + fc + log_softmax ----------------
__global__ void __launch_bounds__(256) pool_fc_kernel(const float* __restrict__ fcw,
                                                      const float* __restrict__ fcb,
                                                      float* __restrict__ out) {
    int g = blockIdx.x;
    int t = threadIdx.x;
    int c = t & 63, rep = t >> 6;
    int s = g_goff[g], e = g_goff[g + 1];
    float sum = 0.f;
    for (int i = s + rep; i < e; i += 4)
        sum += g_o2[(size_t)i * HID + c];
    __shared__ float red[256];
    red[t] = sum;
    __syncthreads();
    if (t < 64) {
        float tot = red[t] + red[t + 64] + red[t + 128] + red[t + 192];
        float cnt = (float)max(e - s, 1);
        float pooled = tot / cnt;
        red[t]      = pooled * fcw[c * 2 + 0];
        red[t + 64] = pooled * fcw[c * 2 + 1];
    }
    __syncthreads();
    if (t < 2) {
        float l = fcb[t];
        for (int i = 0; i < 64; i++) l += red[t * 64 + i];
        red[128 + t] = l;
    }
    __syncthreads();
    if (t == 0) {
        float l0 = red[128], l1 = red[129];
        float m = fmaxf(l0, l1);
        float lse = m + logf(__expf(l0 - m) + __expf(l1 - m));
        out[g * 2 + 0] = l0 - lse;
        out[g * 2 + 1] = l1 - lse;
    }
}

// ---------------- launch ----------------
extern "C" void kernel_launch(void* const* d_in, const int* in_sizes, int n_in,
                              void* d_out, int out_size) {
    const float* x    = (const float*)d_in[0];
    const int*   ei   = (const int*)d_in[1];
    const int*   bat  = (const int*)d_in[2];
    const float* W1   = (const float*)d_in[3];
    const float* as1  = (const float*)d_in[4];
    const float* ad1  = (const float*)d_in[5];
    const float* b1   = (const float*)d_in[6];
    const float* W2   = (const float*)d_in[7];
    const float* as2  = (const float*)d_in[8];
    const float* ad2  = (const float*)d_in[9];
    const float* b2   = (const float*)d_in[10];
    const float* fcw  = (const float*)d_in[11];
    const float* fcb  = (const float*)d_in[12];
    float* out = (float*)d_out;

    __half* xhp;  cudaGetSymbolAddress((void**)&xhp,  g_xh);
    __half* w1hp; cudaGetSymbolAddress((void**)&w1hp, g_W1h);
    __half* w2hp; cudaGetSymbolAddress((void**)&w2hp, g_W2h);
    __half* h1p;  cudaGetSymbolAddress((void**)&h1p,  g_h1h);
    __half* o1p;  cudaGetSymbolAddress((void**)&o1p,  g_o1h);
    __half* h2p;  cudaGetSymbolAddress((void**)&h2p,  g_h2h);

    // converts + CSR build
    f2h_kernel<<<(N_NODES * F_IN / 4 + 255) / 256, 256>>>(x, xhp, N_NODES * F_IN);
    f2h_kernel<<<(F_IN * C1 / 4 + 255) / 256, 256>>>(W1, w1hp, F_IN * C1);
    f2h_kernel<<<(C1 * HID / 4 + 255) / 256, 256>>>(W2, w2hp, C1 * HID);
    zero_kernel<<<128, 256>>>();
    hist_kernel<<<(N_EDGES + 255) / 256, 256>>>(ei);
    scan_kernel<<<1, 1024>>>();
    scatter_kernel<<<(N_EDGES + 255) / 256, 256>>>(ei);

    // layer 1
    dim3 g1(C1 / 64, (N_NODES + 127) / 128);
    gemm_hmma_kernel<<<g1, 256>>>(xhp, w1hp, h1p, N_NODES, C1, F_IN);
    scores1_kernel<<<(N_NODES * HEADS * 32 + 255) / 256, 256>>>(as1, ad1);
    aggregate1_kernel<<<N_NODES, 256>>>(b1);

    // layer 2
    dim3 g2(HID / 64, (N_NODES + 127) / 128);
    gemm_hmma_kernel<<<g2, 256>>>(o1p, w2hp, h2p, N_NODES, HID, C1);
    scores2_kernel<<<(N_NODES * 32 + 255) / 256, 256>>>(as2, ad2);
    aggregate2_kernel<<<N_NODES, 128>>>(b2);

    // pool + classifier
    graph_offsets_kernel<<<1, 128>>>(bat);
    pool_fc_kernel<<<NG, 256>>>(fcw, fcb, out);
}

// round 6
// speedup vs baseline: 1.6832x; 1.0217x over previous
#include <cuda_runtime.h>
#include <cuda_fp16.h>
#include <cstdint>
#include <math.h>

// ---------------- problem constants ----------------
#define N_NODES   50000
#define N_EDGES0  800000
#define N_EDGES   850000      // + self loops
#define F_IN      128
#define HID       64
#define HEADS     4
#define C1        256         // HEADS*HID
#define NG        64
#define SLOPE     0.2f

// ---------------- scratch (device globals) ----------------
__device__ __align__(16) __half g_xh[(size_t)N_NODES * F_IN];   // x (fp16)
__device__ __align__(16) __half g_W1h[F_IN * C1];
__device__ __align__(16) __half g_W2h[C1 * HID];
__device__ __align__(16) __half g_h1h[(size_t)N_NODES * C1];    // x @ W1 (fp16)
__device__ __align__(16) __half g_o1h[(size_t)N_NODES * C1];    // layer-1 out (fp16)
__device__ __align__(16) __half g_h2h[(size_t)N_NODES * HID];   // o1 @ W2 (fp16)
__device__ __align__(16) float  g_o2[(size_t)N_NODES * HID];    // layer-2 out (fp32)

__device__ __align__(16) float g_ssrc1[N_NODES * HEADS];
__device__ __align__(16) float g_sdst1[N_NODES * HEADS];
__device__ float g_ssrc2[N_NODES];
__device__ float g_sdst2[N_NODES];

__device__ int g_deg[N_NODES];
__device__ int g_cursor[N_NODES];
__device__ int g_rowptr[N_NODES + 1];
__device__ int g_esrc[N_EDGES];
__device__ int g_goff[NG + 1];

// ---------------- fp32 -> fp16 convert (n % 4 == 0) ----------------
__global__ void f2h_kernel(const float* __restrict__ in, __half* __restrict__ out, int n) {
    int i = (blockIdx.x * blockDim.x + threadIdx.x) * 4;
    if (i >= n) return;
    float4 v = *(const float4*)(in + i);
    __half2 a = __floats2half2_rn(v.x, v.y);
    __half2 b = __floats2half2_rn(v.z, v.w);
    uint2 u;
    u.x = *(unsigned int*)&a;
    u.y = *(unsigned int*)&b;
    *(uint2*)(out + i) = u;
}

// ---------------- CSR build ----------------
__global__ void hist_kernel(const int* __restrict__ ei) {
    int e = blockIdx.x * blockDim.x + threadIdx.x;
    if (e >= N_EDGES) return;
    int dst = (e < N_EDGES0) ? ei[N_EDGES0 + e] : (e - N_EDGES0);
    atomicAdd(&g_deg[dst], 1);
}

__global__ void scan_kernel() {
    __shared__ int warpsums[32];
    __shared__ int s_carry;
    int t = threadIdx.x;
    int lane = t & 31, warp = t >> 5;
    if (t == 0) s_carry = 0;
    __syncthreads();
    for (int base = 0; base < N_NODES; base += 4096) {
        int i0 = base + t * 4;
        int v[4];
        #pragma unroll
        for (int j = 0; j < 4; j++) v[j] = (i0 + j < N_NODES) ? g_deg[i0 + j] : 0;
        int s = v[0] + v[1] + v[2] + v[3];
        int x = s;
        #pragma unroll
        for (int o = 1; o < 32; o <<= 1) {
            int y = __shfl_up_sync(0xffffffffu, x, o);
            if (lane >= o) x += y;
        }
        if (lane == 31) warpsums[warp] = x;
        __syncthreads();
        if (warp == 0) {
            int w = warpsums[lane];
            #pragma unroll
            for (int o = 1; o < 32; o <<= 1) {
                int y = __shfl_up_sync(0xffffffffu, w, o);
                if (lane >= o) w += y;
            }
            warpsums[lane] = w;
        }
        __syncthreads();
        int excl = x - s + (warp ? warpsums[warp - 1] : 0) + s_carry;
        int run = excl;
        #pragma unroll
        for (int j = 0; j < 4; j++) {
            if (i0 + j < N_NODES) g_rowptr[i0 + j] = run;
            run += v[j];
        }
        int total = warpsums[31];
        __syncthreads();
        if (t == 0) s_carry += total;
        __syncthreads();
    }
    if (t == 0) g_rowptr[N_NODES] = s_carry;
}

__global__ void scatter_kernel(const int* __restrict__ ei) {
    int e = blockIdx.x * blockDim.x + threadIdx.x;
    if (e >= N_EDGES) return;
    int src, dst;
    if (e < N_EDGES0) { src = ei[e]; dst = ei[N_EDGES0 + e]; }
    else { src = e - N_EDGES0; dst = src; }
    int pos = g_rowptr[dst] + atomicAdd(&g_cursor[dst], 1);
    g_esrc[pos] = src;
}

// ---------------- fp16 HMMA GEMM ----------------
#define ASTR 40   // half stride of As row (80B)
#define BSTR 72   // half stride of Bs row (144B)

__device__ __forceinline__ unsigned int smem_u32(const void* p) {
    return (unsigned int)__cvta_generic_to_shared(p);
}

__device__ __forceinline__ void ldsm_x4(unsigned int* r, unsigned int addr) {
    asm volatile("ldmatrix.sync.aligned.m8n8.x4.shared.b16 {%0,%1,%2,%3}, [%4];"
                 : "=r"(r[0]), "=r"(r[1]), "=r"(r[2]), "=r"(r[3]) : "r"(addr));
}

__device__ __forceinline__ void ldsm_x4_t(unsigned int* r, unsigned int addr) {
    asm volatile("ldmatrix.sync.aligned.m8n8.x4.trans.shared.b16 {%0,%1,%2,%3}, [%4];"
                 : "=r"(r[0]), "=r"(r[1]), "=r"(r[2]), "=r"(r[3]) : "r"(addr));
}

__device__ __forceinline__ void mma_f16(float* d, const unsigned int* a,
                                        unsigned int b0, unsigned int b1) {
    asm volatile(
        "mma.sync.aligned.m16n8k16.row.col.f32.f16.f16.f32 "
        "{%0,%1,%2,%3}, {%4,%5,%6,%7}, {%8,%9}, {%0,%1,%2,%3};"
        : "+f"(d[0]), "+f"(d[1]), "+f"(d[2]), "+f"(d[3])
        : "r"(a[0]), "r"(a[1]), "r"(a[2]), "r"(a[3]), "r"(b0), "r"(b1));
}

__global__ void __launch_bounds__(256) gemm_hmma_kernel(
    const __half* __restrict__ A, const __half* __restrict__ B, __half* __restrict__ C,
    int M, int Nn, int K)
{
    __shared__ __half As[128 * ASTR];
    __shared__ __half Bs[32 * BSTR];

    int t = threadIdx.x;
    int lane = t & 31, w = t >> 5;
    int wm = w >> 1, wn = w & 1;
    int bm = blockIdx.y * 128, bn = blockIdx.x * 64;

    float acc[2][4][4] = {};

    for (int kk = 0; kk < K; kk += 32) {
        {
            int row = t >> 1, ch = t & 1;
            int gm = bm + row;
            uint4 v0 = make_uint4(0, 0, 0, 0), v1 = v0;
            if (gm < M) {
                const uint4* src = (const uint4*)(A + (size_t)gm * K + kk + ch * 16);
                v0 = src[0]; v1 = src[1];
            }
            *(uint4*)&As[row * ASTR + ch * 16] = v0;
            *(uint4*)&As[row * ASTR + ch * 16 + 8] = v1;
        }
        {
            int row = t >> 3, ch = t & 7;
            uint4 v = *(const uint4*)(B + (size_t)(kk + row) * Nn + bn + ch * 8);
            *(uint4*)&Bs[row * BSTR + ch * 8] = v;
        }
        __syncthreads();
        #pragma unroll
        for (int ks = 0; ks < 2; ks++) {
            unsigned int a[2][4], b[2][4];
            #pragma unroll
            for (int mt = 0; mt < 2; mt++) {
                unsigned int addr = smem_u32(
                    &As[(wm * 32 + mt * 16 + (lane & 15)) * ASTR + ks * 16 + (lane >> 4) * 8]);
                ldsm_x4(a[mt], addr);
            }
            #pragma unroll
            for (int np = 0; np < 2; np++) {
                unsigned int addr = smem_u32(
                    &Bs[(ks * 16 + (lane & 15)) * BSTR + wn * 32 + np * 16 + (lane >> 4) * 8]);
                ldsm_x4_t(b[np], addr);
            }
            #pragma unroll
            for (int mt = 0; mt < 2; mt++)
                #pragma unroll
                for (int nt = 0; nt < 4; nt++)
                    mma_f16(acc[mt][nt], a[mt], b[nt >> 1][(nt & 1) * 2], b[nt >> 1][(nt & 1) * 2 + 1]);
        }
        __syncthreads();
    }
    #pragma unroll
    for (int mt = 0; mt < 2; mt++) {
        int r0 = bm + wm * 32 + mt * 16 + (lane >> 2);
        #pragma unroll
        for (int nt = 0; nt < 4; nt++) {
            int c0 = bn + wn * 32 + nt * 8 + (lane & 3) * 2;
            if (r0 < M)
                *(__half2*)(C + (size_t)r0 * Nn + c0) =
                    __floats2half2_rn(acc[mt][nt][0], acc[mt][nt][1]);
            if (r0 + 8 < M)
                *(__half2*)(C + (size_t)(r0 + 8) * Nn + c0) =
                    __floats2half2_rn(acc[mt][nt][2], acc[mt][nt][3]);
        }
    }
}

// ---------------- attention scores ----------------
__global__ void scores1_kernel(const float* __restrict__ asrc, const float* __restrict__ adst) {
    int gw = (blockIdx.x * blockDim.x + threadIdx.x) >> 5;
    int lane = threadIdx.x & 31;
    if (gw >= N_NODES * HEADS) return;
    int n = gw >> 2, h = gw & 3;
    const __half* hp = g_h1h + (size_t)n * C1 + h * HID;
    float v0 = __half2float(hp[lane]), v1 = __half2float(hp[lane + 32]);
    float s1 = v0 * asrc[h * HID + lane] + v1 * asrc[h * HID + lane + 32];
    float s2 = v0 * adst[h * HID + lane] + v1 * adst[h * HID + lane + 32];
    #pragma unroll
    for (int o = 16; o; o >>= 1) {
        s1 += __shfl_down_sync(0xffffffffu, s1, o);
        s2 += __shfl_down_sync(0xffffffffu, s2, o);
    }
    if (lane == 0) {
        g_ssrc1[n * 4 + h] = s1;
        g_sdst1[n * 4 + h] = s2;
    }
}

__global__ void scores2_kernel(const float* __restrict__ asrc, const float* __restrict__ adst) {
    int gw = (blockIdx.x * blockDim.x + threadIdx.x) >> 5;
    int lane = threadIdx.x & 31;
    if (gw >= N_NODES) return;
    const __half* hp = g_h2h + (size_t)gw * HID;
    float v0 = __half2float(hp[lane]), v1 = __half2float(hp[lane + 32]);
    float s1 = v0 * asrc[lane] + v1 * asrc[lane + 32];
    float s2 = v0 * adst[lane] + v1 * adst[lane + 32];
    #pragma unroll
    for (int o = 16; o; o >>= 1) {
        s1 += __shfl_down_sync(0xffffffffu, s1, o);
        s2 += __shfl_down_sync(0xffffffffu, s2, o);
    }
    if (lane == 0) {
        g_ssrc2[gw] = s1;
        g_sdst2[gw] = s2;
    }
}

// ---------------- aggregation layer 1 (fp16 gather, fp16 out) ----------------
// block 256 = 4 edge-groups x 64 lanes; weight phase: 1 thread per edge (float4 scores);
// gather phase unrolled x2 for MLP.
#define CH1 64
__global__ void __launch_bounds__(256) aggregate1_kernel(const float* __restrict__ b1) {
    int n = blockIdx.x;
    int t = threadIdx.x;
    int g = t >> 6, l = t & 63;
    int h = l >> 4;
    int r0 = g_rowptr[n], r1 = g_rowptr[n + 1];

    __shared__ float wsh[CH1][HEADS];
    __shared__ int   ssh[CH1];
    __shared__ float4 sacc[256];
    __shared__ float sden[4][HEADS];

    float4 dv = *(const float4*)&g_sdst1[n * 4];
    float4 acc = make_float4(0.f, 0.f, 0.f, 0.f);
    float den = 0.f;

    for (int base = r0; base < r1; base += CH1) {
        int cnt = min(CH1, r1 - base);
        __syncthreads();
        if (t < cnt) {
            int src = g_esrc[base + t];
            ssh[t] = src;
            float4 sv = *(const float4*)&g_ssrc1[src * 4];
            float s0 = sv.x + dv.x; s0 = s0 > 0.f ? s0 : SLOPE * s0;
            float s1 = sv.y + dv.y; s1 = s1 > 0.f ? s1 : SLOPE * s1;
            float s2 = sv.z + dv.z; s2 = s2 > 0.f ? s2 : SLOPE * s2;
            float s3 = sv.w + dv.w; s3 = s3 > 0.f ? s3 : SLOPE * s3;
            *(float4*)&wsh[t][0] =
                make_float4(__expf(s0), __expf(s1), __expf(s2), __expf(s3));
        }
        __syncthreads();
        int e = g;
        for (; e + 4 < cnt; e += 8) {
            float w0 = wsh[e][h];
            float w1 = wsh[e + 4][h];
            uint2 u0 = *(const uint2*)(g_h1h + (size_t)ssh[e] * C1 + l * 4);
            uint2 u1 = *(const uint2*)(g_h1h + (size_t)ssh[e + 4] * C1 + l * 4);
            float2 a0 = __half22float2(*(__half2*)&u0.x);
            float2 a1 = __half22float2(*(__half2*)&u0.y);
            float2 b0 = __half22float2(*(__half2*)&u1.x);
            float2 b1 = __half22float2(*(__half2*)&u1.y);
            acc.x += w0 * a0.x + w1 * b0.x;
            acc.y += w0 * a0.y + w1 * b0.y;
            acc.z += w0 * a1.x + w1 * b1.x;
            acc.w += w0 * a1.y + w1 * b1.y;
            den += w0 + w1;
        }
        if (e < cnt) {
            float w0 = wsh[e][h];
            uint2 u0 = *(const uint2*)(g_h1h + (size_t)ssh[e] * C1 + l * 4);
            float2 a0 = __half22float2(*(__half2*)&u0.x);
            float2 a1 = __half22float2(*(__half2*)&u0.y);
            acc.x += w0 * a0.x; acc.y += w0 * a0.y;
            acc.z += w0 * a1.x; acc.w += w0 * a1.y;
            den += w0;
        }
    }
    sacc[t] = acc;
    if ((l & 15) == 0) sden[g][h] = den;
    __syncthreads();
    if (t < 64) {
        float4 a0 = sacc[l], a1 = sacc[64 + l], a2 = sacc[128 + l], a3 = sacc[192 + l];
        float d = sden[0][h] + sden[1][h] + sden[2][h] + sden[3][h] + 1e-16f;
        float inv = 1.f / d;
        float4 bb = ((const float4*)b1)[l];
        float4 o;
        o.x = (a0.x + a1.x + a2.x + a3.x) * inv + bb.x;
        o.y = (a0.y + a1.y + a2.y + a3.y) * inv + bb.y;
        o.z = (a0.z + a1.z + a2.z + a3.z) * inv + bb.z;
        o.w = (a0.w + a1.w + a2.w + a3.w) * inv + bb.w;
        o.x = o.x > 0.f ? o.x : expm1f(o.x);
        o.y = o.y > 0.f ? o.y : expm1f(o.y);
        o.z = o.z > 0.f ? o.z : expm1f(o.z);
        o.w = o.w > 0.f ? o.w : expm1f(o.w);
        __half2 p0 = __floats2half2_rn(o.x, o.y);
        __half2 p1 = __floats2half2_rn(o.z, o.w);
        uint2 u;
        u.x = *(unsigned int*)&p0;
        u.y = *(unsigned int*)&p1;
        ((uint2*)(g_o1h + (size_t)n * C1))[l] = u;
    }
}

// ---------------- aggregation layer 2 (fp16 gather, fp32 out) ----------------
#define CH2 64
__global__ void __launch_bounds__(128) aggregate2_kernel(const float* __restrict__ b2) {
    int n = blockIdx.x;
    int t = threadIdx.x;
    int g = t >> 4, l = t & 15;
    int r0 = g_rowptr[n], r1 = g_rowptr[n + 1];

    __shared__ float wsh[CH2];
    __shared__ int   ssh[CH2];
    __shared__ float4 sacc[128];
    __shared__ float sden[8];

    float sd = g_sdst2[n];
    float4 acc = make_float4(0.f, 0.f, 0.f, 0.f);
    float den = 0.f;

    for (int base = r0; base < r1; base += CH2) {
        int cnt = min(CH2, r1 - base);
        __syncthreads();
        if (t < cnt) {
            int src = g_esrc[base + t];
            ssh[t] = src;
            float s = g_ssrc2[src] + sd;
            s = s > 0.f ? s : SLOPE * s;
            wsh[t] = __expf(s);
        }
        __syncthreads();
        int e = g;
        for (; e + 8 < cnt; e += 16) {
            float w0 = wsh[e], w1 = wsh[e + 8];
            uint2 u0 = *(const uint2*)(g_h2h + (size_t)ssh[e] * HID + l * 4);
            uint2 u1 = *(const uint2*)(g_h2h + (size_t)ssh[e + 8] * HID + l * 4);
            float2 a0 = __half22float2(*(__half2*)&u0.x);
            float2 a1 = __half22float2(*(__half2*)&u0.y);
            float2 b0 = __half22float2(*(__half2*)&u1.x);
            float2 b1 = __half22float2(*(__half2*)&u1.y);
            acc.x += w0 * a0.x + w1 * b0.x;
            acc.y += w0 * a0.y + w1 * b0.y;
            acc.z += w0 * a1.x + w1 * b1.x;
            acc.w += w0 * a1.y + w1 * b1.y;
            den += w0 + w1;
        }
        if (e < cnt) {
            float w0 = wsh[e];
            uint2 u0 = *(const uint2*)(g_h2h + (size_t)ssh[e] * HID + l * 4);
            float2 a0 = __half22float2(*(__half2*)&u0.x);
            float2 a1 = __half22float2(*(__half2*)&u0.y);
            acc.x += w0 * a0.x; acc.y += w0 * a0.y;
            acc.z += w0 * a1.x; acc.w += w0 * a1.y;
            den += w0;
        }
    }
    sacc[t] = acc;
    if (l == 0) sden[g] = den;
    __syncthreads();
    if (t < 16) {
        float4 a = make_float4(0.f, 0.f, 0.f, 0.f);
        float d = 1e-16f;
        #pragma unroll
        for (int gg = 0; gg < 8; gg++) {
            float4 v = sacc[gg * 16 + l];
            a.x += v.x; a.y += v.y; a.z += v.z; a.w += v.w;
            d += sden[gg];
        }
        float inv = 1.f / d;
        float4 bb = ((const float4*)b2)[l];
        float4 o;
        o.x = a.x * inv + bb.x; o.y = a.y * inv + bb.y;
        o.z = a.z * inv + bb.z; o.w = a.w * inv + bb.w;
        o.x = o.x > 0.f ? o.x : expm1f(o.x);
        o.y = o.y > 0.f ? o.y : expm1f(o.y);
        o.z = o.z > 0.f ? o.z : expm1f(o.z);
        o.w = o.w > 0.f ? o.w : expm1f(o.w);
        ((float4*)(g_o2 + (size_t)n * HID))[l] = o;
    }
}

// ---------------- graph offsets ----------------
__global__ void graph_offsets_kernel(const int* __restrict__ batch) {
    int g = blockIdx.x * blockDim.x + threadIdx.x;
    if (g > NG) return;
    if (g == NG) { g_goff[NG] = N_NODES; return; }
    int lo = 0, hi = N_NODES;
    while (lo < hi) {
        int mid = (lo + hi) >> 1;
        if (batch[mid] < g) lo = mid + 1; else hi = mid;
    }
    g_goff[g] = lo;
}

// ---------------- pool + fc + log_softmax ----------------
__global__ void __launch_bounds__(256) pool_fc_kernel(const float* __restrict__ fcw,
                                                      const float* __restrict__ fcb,
                                                      float* __restrict__ out) {
    int g = blockIdx.x;
    int t = threadIdx.x;
    int c = t & 63, rep = t >> 6;
    int s = g_goff[g], e = g_goff[g + 1];
    float sum = 0.f;
    for (int i = s + rep; i < e; i += 4)
        sum += g_o2[(size_t)i * HID + c];
    __shared__ float red[256];
    red[t] = sum;
    __syncthreads();
    if (t < 64) {
        float tot = red[t] + red[t + 64] + red[t + 128] + red[t + 192];
        float cnt = (float)max(e - s, 1);
        float pooled = tot / cnt;
        red[t]      = pooled * fcw[c * 2 + 0];
        red[t + 64] = pooled * fcw[c * 2 + 1];
    }
    __syncthreads();
    if (t < 2) {
        float l = fcb[t];
        for (int i = 0; i < 64; i++) l += red[t * 64 + i];
        red[128 + t] = l;
    }
    __syncthreads();
    if (t == 0) {
        float l0 = red[128], l1 = red[129];
        float m = fmaxf(l0, l1);
        float lse = m + logf(__expf(l0 - m) + __expf(l1 - m));
        out[g * 2 + 0] = l0 - lse;
        out[g * 2 + 1] = l1 - lse;
    }
}

// ---------------- launch ----------------
extern "C" void kernel_launch(void* const* d_in, const int* in_sizes, int n_in,
                              void* d_out, int out_size) {
    const float* x    = (const float*)d_in[0];
    const int*   ei   = (const int*)d_in[1];
    const int*   bat  = (const int*)d_in[2];
    const float* W1   = (const float*)d_in[3];
    const float* as1  = (const float*)d_in[4];
    const float* ad1  = (const float*)d_in[5];
    const float* b1   = (const float*)d_in[6];
    const float* W2   = (const float*)d_in[7];
    const float* as2  = (const float*)d_in[8];
    const float* ad2  = (const float*)d_in[9];
    const float* b2   = (const float*)d_in[10];
    const float* fcw  = (const float*)d_in[11];
    const float* fcb  = (const float*)d_in[12];
    float* out = (float*)d_out;

    __half* xhp;  cudaGetSymbolAddress((void**)&xhp,  g_xh);
    __half* w1hp; cudaGetSymbolAddress((void**)&w1hp, g_W1h);
    __half* w2hp; cudaGetSymbolAddress((void**)&w2hp, g_W2h);
    __half* h1p;  cudaGetSymbolAddress((void**)&h1p,  g_h1h);
    __half* o1p;  cudaGetSymbolAddress((void**)&o1p,  g_o1h);
    __half* h2p;  cudaGetSymbolAddress((void**)&h2p,  g_h2h);
    int* degp;    cudaGetSymbolAddress((void**)&degp, g_deg);
    int* curp;    cudaGetSymbolAddress((void**)&curp, g_cursor);

    // side stream + events for fork/join inside graph capture
    // (kernel_launch runs only a handful of times — correctness + capture —
    //  so the created objects are few; replays re-use the captured graph)
    cudaStream_t side;
    cudaStreamCreateWithFlags(&side, cudaStreamNonBlocking);
    cudaEvent_t evF, evJ;
    cudaEventCreateWithFlags(&evF, cudaEventDisableTiming);
    cudaEventCreateWithFlags(&evJ, cudaEventDisableTiming);

    // fork: CSR build on side stream
    cudaEventRecord(evF, 0);
    cudaStreamWaitEvent(side, evF, 0);
    cudaMemsetAsync(degp, 0, N_NODES * sizeof(int), side);
    cudaMemsetAsync(curp, 0, N_NODES * sizeof(int), side);
    hist_kernel<<<(N_EDGES + 255) / 256, 256, 0, side>>>(ei);
    scan_kernel<<<1, 1024, 0, side>>>();
    scatter_kernel<<<(N_EDGES + 255) / 256, 256, 0, side>>>(ei);
    cudaEventRecord(evJ, side);

    // main: converts + gemm1 + scores1
    f2h_kernel<<<(N_NODES * F_IN / 4 + 255) / 256, 256>>>(x, xhp, N_NODES * F_IN);
    f2h_kernel<<<(F_IN * C1 / 4 + 255) / 256, 256>>>(W1, w1hp, F_IN * C1);
    f2h_kernel<<<(C1 * HID / 4 + 255) / 256, 256>>>(W2, w2hp, C1 * HID);
    graph_offsets_kernel<<<1, 128>>>(bat);

    dim3 g1(C1 / 64, (N_NODES + 127) / 128);
    gemm_hmma_kernel<<<g1, 256>>>(xhp, w1hp, h1p, N_NODES, C1, F_IN);
    scores1_kernel<<<(N_NODES * HEADS * 32 + 255) / 256, 256>>>(as1, ad1);

    // join: aggregate1 needs CSR + scores
    cudaStreamWaitEvent(0, evJ, 0);
    aggregate1_kernel<<<N_NODES, 256>>>(b1);

    // layer 2
    dim3 g2(HID / 64, (N_NODES + 127) / 128);
    gemm_hmma_kernel<<<g2, 256>>>(o1p, w2hp, h2p, N_NODES, HID, C1);
    scores2_kernel<<<(N_NODES * 32 + 255) / 256, 256>>>(as2, ad2);
    aggregate2_kernel<<<N_NODES, 128>>>(b2);

    // pool + classifier
    pool_fc_kernel<<<NG, 256>>>(fcw, fcb, out);
}

// round 7
// speedup vs baseline: 1.6833x; 1.0001x over previous
#include <cuda_runtime.h>
#include <cuda_fp16.h>
#include <cstdint>
#include <math.h>

// ---------------- problem constants ----------------
#define N_NODES   50000
#define N_EDGES0  800000
#define N_EDGES   850000      // + self loops
#define F_IN      128
#define HID       64
#define HEADS     4
#define C1        256         // HEADS*HID
#define NG        64
#define SLOPE     0.2f

// ---------------- scratch (device globals) ----------------
__device__ __align__(16) __half g_xh[(size_t)N_NODES * F_IN];   // x (fp16)
__device__ __align__(16) __half g_W1h[F_IN * C1];
__device__ __align__(16) __half g_W2h[C1 * HID];
__device__ __align__(16) __half g_h1h[(size_t)N_NODES * C1];    // x @ W1 (fp16)
__device__ __align__(16) __half g_o1h[(size_t)N_NODES * C1];    // layer-1 out (fp16)
__device__ __align__(16) __half g_h2h[(size_t)N_NODES * HID];   // o1 @ W2 (fp16)
__device__ __align__(16) float  g_o2[(size_t)N_NODES * HID];    // layer-2 out (fp32)

__device__ __align__(16) float g_ssrc1[N_NODES * HEADS];
__device__ __align__(16) float g_sdst1[N_NODES * HEADS];
__device__ float g_ssrc2[N_NODES];
__device__ float g_sdst2[N_NODES];

__device__ int g_deg[N_NODES];
__device__ int g_cursor[N_NODES];
__device__ int g_rowptr[N_NODES + 1];
__device__ int g_esrc[N_EDGES];
__device__ int g_goff[NG + 1];

// ---------------- fp32 -> fp16 convert (n % 4 == 0) ----------------
__global__ void f2h_kernel(const float* __restrict__ in, __half* __restrict__ out, int n) {
    int i = (blockIdx.x * blockDim.x + threadIdx.x) * 4;
    if (i >= n) return;
    float4 v = *(const float4*)(in + i);
    __half2 a = __floats2half2_rn(v.x, v.y);
    __half2 b = __floats2half2_rn(v.z, v.w);
    uint2 u;
    u.x = *(unsigned int*)&a;
    u.y = *(unsigned int*)&b;
    *(uint2*)(out + i) = u;
}

// ---------------- CSR build ----------------
__global__ void hist_kernel(const int* __restrict__ ei) {
    int e = blockIdx.x * blockDim.x + threadIdx.x;
    if (e >= N_EDGES) return;
    int dst = (e < N_EDGES0) ? ei[N_EDGES0 + e] : (e - N_EDGES0);
    atomicAdd(&g_deg[dst], 1);
}

__global__ void scan_kernel() {
    __shared__ int warpsums[32];
    __shared__ int s_carry;
    int t = threadIdx.x;
    int lane = t & 31, warp = t >> 5;
    if (t == 0) s_carry = 0;
    __syncthreads();
    for (int base = 0; base < N_NODES; base += 4096) {
        int i0 = base + t * 4;
        int v[4];
        #pragma unroll
        for (int j = 0; j < 4; j++) v[j] = (i0 + j < N_NODES) ? g_deg[i0 + j] : 0;
        int s = v[0] + v[1] + v[2] + v[3];
        int x = s;
        #pragma unroll
        for (int o = 1; o < 32; o <<= 1) {
            int y = __shfl_up_sync(0xffffffffu, x, o);
            if (lane >= o) x += y;
        }
        if (lane == 31) warpsums[warp] = x;
        __syncthreads();
        if (warp == 0) {
            int w = warpsums[lane];
            #pragma unroll
            for (int o = 1; o < 32; o <<= 1) {
                int y = __shfl_up_sync(0xffffffffu, w, o);
                if (lane >= o) w += y;
            }
            warpsums[lane] = w;
        }
        __syncthreads();
        int excl = x - s + (warp ? warpsums[warp - 1] : 0) + s_carry;
        int run = excl;
        #pragma unroll
        for (int j = 0; j < 4; j++) {
            if (i0 + j < N_NODES) g_rowptr[i0 + j] = run;
            run += v[j];
        }
        int total = warpsums[31];
        __syncthreads();
        if (t == 0) s_carry += total;
        __syncthreads();
    }
    if (t == 0) g_rowptr[N_NODES] = s_carry;
}

__global__ void scatter_kernel(const int* __restrict__ ei) {
    int e = blockIdx.x * blockDim.x + threadIdx.x;
    if (e >= N_EDGES) return;
    int src, dst;
    if (e < N_EDGES0) { src = ei[e]; dst = ei[N_EDGES0 + e]; }
    else { src = e - N_EDGES0; dst = src; }
    int pos = g_rowptr[dst] + atomicAdd(&g_cursor[dst], 1);
    g_esrc[pos] = src;
}

// ---------------- fp16 HMMA GEMM ----------------
#define ASTR 40   // half stride of As row (80B)
#define BSTR 72   // half stride of Bs row (144B)

__device__ __forceinline__ unsigned int smem_u32(const void* p) {
    return (unsigned int)__cvta_generic_to_shared(p);
}

__device__ __forceinline__ void ldsm_x4(unsigned int* r, unsigned int addr) {
    asm volatile("ldmatrix.sync.aligned.m8n8.x4.shared.b16 {%0,%1,%2,%3}, [%4];"
                 : "=r"(r[0]), "=r"(r[1]), "=r"(r[2]), "=r"(r[3]) : "r"(addr));
}

__device__ __forceinline__ void ldsm_x4_t(unsigned int* r, unsigned int addr) {
    asm volatile("ldmatrix.sync.aligned.m8n8.x4.trans.shared.b16 {%0,%1,%2,%3}, [%4];"
                 : "=r"(r[0]), "=r"(r[1]), "=r"(r[2]), "=r"(r[3]) : "r"(addr));
}

__device__ __forceinline__ void mma_f16(float* d, const unsigned int* a,
                                        unsigned int b0, unsigned int b1) {
    asm volatile(
        "mma.sync.aligned.m16n8k16.row.col.f32.f16.f16.f32 "
        "{%0,%1,%2,%3}, {%4,%5,%6,%7}, {%8,%9}, {%0,%1,%2,%3};"
        : "+f"(d[0]), "+f"(d[1]), "+f"(d[2]), "+f"(d[3])
        : "r"(a[0]), "r"(a[1]), "r"(a[2]), "r"(a[3]), "r"(b0), "r"(b1));
}

__global__ void __launch_bounds__(256) gemm_hmma_kernel(
    const __half* __restrict__ A, const __half* __restrict__ B, __half* __restrict__ C,
    int M, int Nn, int K)
{
    __shared__ __half As[128 * ASTR];
    __shared__ __half Bs[32 * BSTR];

    int t = threadIdx.x;
    int lane = t & 31, w = t >> 5;
    int wm = w >> 1, wn = w & 1;
    int bm = blockIdx.y * 128, bn = blockIdx.x * 64;

    float acc[2][4][4] = {};

    for (int kk = 0; kk < K; kk += 32) {
        {
            int row = t >> 1, ch = t & 1;
            int gm = bm + row;
            uint4 v0 = make_uint4(0, 0, 0, 0), v1 = v0;
            if (gm < M) {
                const uint4* src = (const uint4*)(A + (size_t)gm * K + kk + ch * 16);
                v0 = src[0]; v1 = src[1];
            }
            *(uint4*)&As[row * ASTR + ch * 16] = v0;
            *(uint4*)&As[row * ASTR + ch * 16 + 8] = v1;
        }
        {
            int row = t >> 3, ch = t & 7;
            uint4 v = *(const uint4*)(B + (size_t)(kk + row) * Nn + bn + ch * 8);
            *(uint4*)&Bs[row * BSTR + ch * 8] = v;
        }
        __syncthreads();
        #pragma unroll
        for (int ks = 0; ks < 2; ks++) {
            unsigned int a[2][4], b[2][4];
            #pragma unroll
            for (int mt = 0; mt < 2; mt++) {
                unsigned int addr = smem_u32(
                    &As[(wm * 32 + mt * 16 + (lane & 15)) * ASTR + ks * 16 + (lane >> 4) * 8]);
                ldsm_x4(a[mt], addr);
            }
            #pragma unroll
            for (int np = 0; np < 2; np++) {
                unsigned int addr = smem_u32(
                    &Bs[(ks * 16 + (lane & 15)) * BSTR + wn * 32 + np * 16 + (lane >> 4) * 8]);
                ldsm_x4_t(b[np], addr);
            }
            #pragma unroll
            for (int mt = 0; mt < 2; mt++)
                #pragma unroll
                for (int nt = 0; nt < 4; nt++)
                    mma_f16(acc[mt][nt], a[mt], b[nt >> 1][(nt & 1) * 2], b[nt >> 1][(nt & 1) * 2 + 1]);
        }
        __syncthreads();
    }
    #pragma unroll
    for (int mt = 0; mt < 2; mt++) {
        int r0 = bm + wm * 32 + mt * 16 + (lane >> 2);
        #pragma unroll
        for (int nt = 0; nt < 4; nt++) {
            int c0 = bn + wn * 32 + nt * 8 + (lane & 3) * 2;
            if (r0 < M)
                *(__half2*)(C + (size_t)r0 * Nn + c0) =
                    __floats2half2_rn(acc[mt][nt][0], acc[mt][nt][1]);
            if (r0 + 8 < M)
                *(__half2*)(C + (size_t)(r0 + 8) * Nn + c0) =
                    __floats2half2_rn(acc[mt][nt][2], acc[mt][nt][3]);
        }
    }
}

// ---------------- attention scores ----------------
__global__ void scores1_kernel(const float* __restrict__ asrc, const float* __restrict__ adst) {
    int gw = (blockIdx.x * blockDim.x + threadIdx.x) >> 5;
    int lane = threadIdx.x & 31;
    if (gw >= N_NODES * HEADS) return;
    int n = gw >> 2, h = gw & 3;
    const __half* hp = g_h1h + (size_t)n * C1 + h * HID;
    float v0 = __half2float(hp[lane]), v1 = __half2float(hp[lane + 32]);
    float s1 = v0 * asrc[h * HID + lane] + v1 * asrc[h * HID + lane + 32];
    float s2 = v0 * adst[h * HID + lane] + v1 * adst[h * HID + lane + 32];
    #pragma unroll
    for (int o = 16; o; o >>= 1) {
        s1 += __shfl_down_sync(0xffffffffu, s1, o);
        s2 += __shfl_down_sync(0xffffffffu, s2, o);
    }
    if (lane == 0) {
        g_ssrc1[n * 4 + h] = s1;
        g_sdst1[n * 4 + h] = s2;
    }
}

__global__ void scores2_kernel(const float* __restrict__ asrc, const float* __restrict__ adst) {
    int gw = (blockIdx.x * blockDim.x + threadIdx.x) >> 5;
    int lane = threadIdx.x & 31;
    if (gw >= N_NODES) return;
    const __half* hp = g_h2h + (size_t)gw * HID;
    float v0 = __half2float(hp[lane]), v1 = __half2float(hp[lane + 32]);
    float s1 = v0 * asrc[lane] + v1 * asrc[lane + 32];
    float s2 = v0 * adst[lane] + v1 * adst[lane + 32];
    #pragma unroll
    for (int o = 16; o; o >>= 1) {
        s1 += __shfl_down_sync(0xffffffffu, s1, o);
        s2 += __shfl_down_sync(0xffffffffu, s2, o);
    }
    if (lane == 0) {
        g_ssrc2[gw] = s1;
        g_sdst2[gw] = s2;
    }
}

// ---------------- aggregation layer 1 (fp16 gather, fp16 out) ----------------
// block 256 = 4 edge-groups x 64 lanes; weight phase: 1 thread per edge (float4 scores);
// gather phase unrolled x2 for MLP.
#define CH1 64
__global__ void __launch_bounds__(256) aggregate1_kernel(const float* __restrict__ b1) {
    int n = blockIdx.x;
    int t = threadIdx.x;
    int g = t >> 6, l = t & 63;
    int h = l >> 4;
    int r0 = g_rowptr[n], r1 = g_rowptr[n + 1];

    __shared__ float wsh[CH1][HEADS];
    __shared__ int   ssh[CH1];
    __shared__ float4 sacc[256];
    __shared__ float sden[4][HEADS];

    float4 dv = *(const float4*)&g_sdst1[n * 4];
    float4 acc = make_float4(0.f, 0.f, 0.f, 0.f);
    float den = 0.f;

    for (int base = r0; base < r1; base += CH1) {
        int cnt = min(CH1, r1 - base);
        __syncthreads();
        if (t < cnt) {
            int src = g_esrc[base + t];
            ssh[t] = src;
            float4 sv = *(const float4*)&g_ssrc1[src * 4];
            float s0 = sv.x + dv.x; s0 = s0 > 0.f ? s0 : SLOPE * s0;
            float s1 = sv.y + dv.y; s1 = s1 > 0.f ? s1 : SLOPE * s1;
            float s2 = sv.z + dv.z; s2 = s2 > 0.f ? s2 : SLOPE * s2;
            float s3 = sv.w + dv.w; s3 = s3 > 0.f ? s3 : SLOPE * s3;
            *(float4*)&wsh[t][0] =
                make_float4(__expf(s0), __expf(s1), __expf(s2), __expf(s3));
        }
        __syncthreads();
        int e = g;
        for (; e + 4 < cnt; e += 8) {
            float w0 = wsh[e][h];
            float w1 = wsh[e + 4][h];
            uint2 u0 = *(const uint2*)(g_h1h + (size_t)ssh[e] * C1 + l * 4);
            uint2 u1 = *(const uint2*)(g_h1h + (size_t)ssh[e + 4] * C1 + l * 4);
            float2 a0 = __half22float2(*(__half2*)&u0.x);
            float2 a1 = __half22float2(*(__half2*)&u0.y);
            float2 b0 = __half22float2(*(__half2*)&u1.x);
            float2 b1 = __half22float2(*(__half2*)&u1.y);
            acc.x += w0 * a0.x + w1 * b0.x;
            acc.y += w0 * a0.y + w1 * b0.y;
            acc.z += w0 * a1.x + w1 * b1.x;
            acc.w += w0 * a1.y + w1 * b1.y;
            den += w0 + w1;
        }
        if (e < cnt) {
            float w0 = wsh[e][h];
            uint2 u0 = *(const uint2*)(g_h1h + (size_t)ssh[e] * C1 + l * 4);
            float2 a0 = __half22float2(*(__half2*)&u0.x);
            float2 a1 = __half22float2(*(__half2*)&u0.y);
            acc.x += w0 * a0.x; acc.y += w0 * a0.y;
            acc.z += w0 * a1.x; acc.w += w0 * a1.y;
            den += w0;
        }
    }
    sacc[t] = acc;
    if ((l & 15) == 0) sden[g][h] = den;
    __syncthreads();
    if (t < 64) {
        float4 a0 = sacc[l], a1 = sacc[64 + l], a2 = sacc[128 + l], a3 = sacc[192 + l];
        float d = sden[0][h] + sden[1][h] + sden[2][h] + sden[3][h] + 1e-16f;
        float inv = 1.f / d;
        float4 bb = ((const float4*)b1)[l];
        float4 o;
        o.x = (a0.x + a1.x + a2.x + a3.x) * inv + bb.x;
        o.y = (a0.y + a1.y + a2.y + a3.y) * inv + bb.y;
        o.z = (a0.z + a1.z + a2.z + a3.z) * inv + bb.z;
        o.w = (a0.w + a1.w + a2.w + a3.w) * inv + bb.w;
        o.x = o.x > 0.f ? o.x : expm1f(o.x);
        o.y = o.y > 0.f ? o.y : expm1f(o.y);
        o.z = o.z > 0.f ? o.z : expm1f(o.z);
        o.w = o.w > 0.f ? o.w : expm1f(o.w);
        __half2 p0 = __floats2half2_rn(o.x, o.y);
        __half2 p1 = __floats2half2_rn(o.z, o.w);
        uint2 u;
        u.x = *(unsigned int*)&p0;
        u.y = *(unsigned int*)&p1;
        ((uint2*)(g_o1h + (size_t)n * C1))[l] = u;
    }
}

// ---------------- aggregation layer 2 (fp16 gather, fp32 out) ----------------
#define CH2 64
__global__ void __launch_bounds__(128) aggregate2_kernel(const float* __restrict__ b2) {
    int n = blockIdx.x;
    int t = threadIdx.x;
    int g = t >> 4, l = t & 15;
    int r0 = g_rowptr[n], r1 = g_rowptr[n + 1];

    __shared__ float wsh[CH2];
    __shared__ int   ssh[CH2];
    __shared__ float4 sacc[128];
    __shared__ float sden[8];

    float sd = g_sdst2[n];
    float4 acc = make_float4(0.f, 0.f, 0.f, 0.f);
    float den = 0.f;

    for (int base = r0; base < r1; base += CH2) {
        int cnt = min(CH2, r1 - base);
        __syncthreads();
        if (t < cnt) {
            int src = g_esrc[base + t];
            ssh[t] = src;
            float s = g_ssrc2[src] + sd;
            s = s > 0.f ? s : SLOPE * s;
            wsh[t] = __expf(s);
        }
        __syncthreads();
        int e = g;
        for (; e + 8 < cnt; e += 16) {
            float w0 = wsh[e], w1 = wsh[e + 8];
            uint2 u0 = *(const uint2*)(g_h2h + (size_t)ssh[e] * HID + l * 4);
            uint2 u1 = *(const uint2*)(g_h2h + (size_t)ssh[e + 8] * HID + l * 4);
            float2 a0 = __half22float2(*(__half2*)&u0.x);
            float2 a1 = __half22float2(*(__half2*)&u0.y);
            float2 b0 = __half22float2(*(__half2*)&u1.x);
            float2 b1 = __half22float2(*(__half2*)&u1.y);
            acc.x += w0 * a0.x + w1 * b0.x;
            acc.y += w0 * a0.y + w1 * b0.y;
            acc.z += w0 * a1.x + w1 * b1.x;
            acc.w += w0 * a1.y + w1 * b1.y;
            den += w0 + w1;
        }
        if (e < cnt) {
            float w0 = wsh[e];
            uint2 u0 = *(const uint2*)(g_h2h + (size_t)ssh[e] * HID + l * 4);
            float2 a0 = __half22float2(*(__half2*)&u0.x);
            float2 a1 = __half22float2(*(__half2*)&u0.y);
            acc.x += w0 * a0.x; acc.y += w0 * a0.y;
            acc.z += w0 * a1.x; acc.w += w0 * a1.y;
            den += w0;
        }
    }
    sacc[t] = acc;
    if (l == 0) sden[g] = den;
    __syncthreads();
    if (t < 16) {
        float4 a = make_float4(0.f, 0.f, 0.f, 0.f);
        float d = 1e-16f;
        #pragma unroll
        for (int gg = 0; gg < 8; gg++) {
            float4 v = sacc[gg * 16 + l];
            a.x += v.x; a.y += v.y; a.z += v.z; a.w += v.w;
            d += sden[gg];
        }
        float inv = 1.f / d;
        float4 bb = ((const float4*)b2)[l];
        float4 o;
        o.x = a.x * inv + bb.x; o.y = a.y * inv + bb.y;
        o.z = a.z * inv + bb.z; o.w = a.w * inv + bb.w;
        o.x = o.x > 0.f ? o.x : expm1f(o.x);
        o.y = o.y > 0.f ? o.y : expm1f(o.y);
        o.z = o.z > 0.f ? o.z : expm1f(o.z);
        o.w = o.w > 0.f ? o.w : expm1f(o.w);
        ((float4*)(g_o2 + (size_t)n * HID))[l] = o;
    }
}

// ---------------- graph offsets ----------------
__global__ void graph_offsets_kernel(const int* __restrict__ batch) {
    int g = blockIdx.x * blockDim.x + threadIdx.x;
    if (g > NG) return;
    if (g == NG) { g_goff[NG] = N_NODES; return; }
    int lo = 0, hi = N_NODES;
    while (lo < hi) {
        int mid = (lo + hi) >> 1;
        if (batch[mid] < g) lo = mid + 1; else hi = mid;
    }
    g_goff[g] = lo;
}

// ---------------- pool + fc + log_softmax ----------------
__global__ void __launch_bounds__(256) pool_fc_kernel(const float* __restrict__ fcw,
                                                      const float* __restrict__ fcb,
                                                      float* __restrict__ out) {
    int g = blockIdx.x;
    int t = threadIdx.x;
    int c = t & 63, rep = t >> 6;
    int s = g_goff[g], e = g_goff[g + 1];
    float sum = 0.f;
    for (int i = s + rep; i < e; i += 4)
        sum += g_o2[(size_t)i * HID + c];
    __shared__ float red[256];
    red[t] = sum;
    __syncthreads();
    if (t < 64) {
        float tot = red[t] + red[t + 64] + red[t + 128] + red[t + 192];
        float cnt = (float)max(e - s, 1);
        float pooled = tot / cnt;
        red[t]      = pooled * fcw[c * 2 + 0];
        red[t + 64] = pooled * fcw[c * 2 + 1];
    }
    __syncthreads();
    if (t < 2) {
        float l = fcb[t];
        for (int i = 0; i < 64; i++) l += red[t * 64 + i];
        red[128 + t] = l;
    }
    __syncthreads();
    if (t == 0) {
        float l0 = red[128], l1 = red[129];
        float m = fmaxf(l0, l1);
        float lse = m + logf(__expf(l0 - m) + __expf(l1 - m));
        out[g * 2 + 0] = l0 - lse;
        out[g * 2 + 1] = l1 - lse;
    }
}

// ---------------- launch ----------------
extern "C" void kernel_launch(void* const* d_in, const int* in_sizes, int n_in,
                              void* d_out, int out_size) {
    const float* x    = (const float*)d_in[0];
    const int*   ei   = (const int*)d_in[1];
    const int*   bat  = (const int*)d_in[2];
    const float* W1   = (const float*)d_in[3];
    const float* as1  = (const float*)d_in[4];
    const float* ad1  = (const float*)d_in[5];
    const float* b1   = (const float*)d_in[6];
    const float* W2   = (const float*)d_in[7];
    const float* as2  = (const float*)d_in[8];
    const float* ad2  = (const float*)d_in[9];
    const float* b2   = (const float*)d_in[10];
    const float* fcw  = (const float*)d_in[11];
    const float* fcb  = (const float*)d_in[12];
    float* out = (float*)d_out;

    __half* xhp;  cudaGetSymbolAddress((void**)&xhp,  g_xh);
    __half* w1hp; cudaGetSymbolAddress((void**)&w1hp, g_W1h);
    __half* w2hp; cudaGetSymbolAddress((void**)&w2hp, g_W2h);
    __half* h1p;  cudaGetSymbolAddress((void**)&h1p,  g_h1h);
    __half* o1p;  cudaGetSymbolAddress((void**)&o1p,  g_o1h);
    __half* h2p;  cudaGetSymbolAddress((void**)&h2p,  g_h2h);
    int* degp;    cudaGetSymbolAddress((void**)&degp, g_deg);
    int* curp;    cudaGetSymbolAddress((void**)&curp, g_cursor);

    // side stream + events for fork/join inside graph capture
    // (kernel_launch runs only a handful of times — correctness + capture —
    //  so the created objects are few; replays re-use the captured graph)
    cudaStream_t side;
    cudaStreamCreateWithFlags(&side, cudaStreamNonBlocking);
    cudaEvent_t evF, evJ;
    cudaEventCreateWithFlags(&evF, cudaEventDisableTiming);
    cudaEventCreateWithFlags(&evJ, cudaEventDisableTiming);

    // fork: CSR build on side stream
    cudaEventRecord(evF, 0);
    cudaStreamWaitEvent(side, evF, 0);
    cudaMemsetAsync(degp, 0, N_NODES * sizeof(int), side);
    cudaMemsetAsync(curp, 0, N_NODES * sizeof(int), side);
    hist_kernel<<<(N_EDGES + 255) / 256, 256, 0, side>>>(ei);
    scan_kernel<<<1, 1024, 0, side>>>();
    scatter_kernel<<<(N_EDGES + 255) / 256, 256, 0, side>>>(ei);
    cudaEventRecord(evJ, side);

    // main: converts + gemm1 + scores1
    f2h_kernel<<<(N_NODES * F_IN / 4 + 255) / 256, 256>>>(x, xhp, N_NODES * F_IN);
    f2h_kernel<<<(F_IN * C1 / 4 + 255) / 256, 256>>>(W1, w1hp, F_IN * C1);
    f2h_kernel<<<(C1 * HID / 4 + 255) / 256, 256>>>(W2, w2hp, C1 * HID);
    graph_offsets_kernel<<<1, 128>>>(bat);

    dim3 g1(C1 / 64, (N_NODES + 127) / 128);
    gemm_hmma_kernel<<<g1, 256>>>(xhp, w1hp, h1p, N_NODES, C1, F_IN);
    scores1_kernel<<<(N_NODES * HEADS * 32 + 255) / 256, 256>>>(as1, ad1);

    // join: aggregate1 needs CSR + scores
    cudaStreamWaitEvent(0, evJ, 0);
    aggregate1_kernel<<<N_NODES, 256>>>(b1);

    // layer 2
    dim3 g2(HID / 64, (N_NODES + 127) / 128);
    gemm_hmma_kernel<<<g2, 256>>>(o1p, w2hp, h2p, N_NODES, HID, C1);
    scores2_kernel<<<(N_NODES * 32 + 255) / 256, 256>>>(as2, ad2);
    aggregate2_kernel<<<N_NODES, 128>>>(b2);

    // pool + classifier
    pool_fc_kernel<<<NG, 256>>>(fcw, fcb, out);
}

// round 8
// speedup vs baseline: 2.4014x; 1.4266x over previous
#include <cuda_runtime.h>
#include <cuda_fp16.h>
#include <cstdint>
#include <math.h>

// ---------------- problem constants ----------------
#define N_NODES   50000
#define N_EDGES0  800000
#define N_EDGES   850000      // + self loops
#define F_IN      128
#define HID       64
#define HEADS     4
#define C1        256         // HEADS*HID
#define NG        64
#define SLOPE     0.2f

// ---------------- scratch (device globals) ----------------
__device__ __align__(16) __half g_W1h[F_IN * C1];
__device__ __align__(16) __half g_W2h[C1 * HID];
__device__ __align__(16) __half g_h1h[(size_t)N_NODES * C1];    // x @ W1 (fp16)
__device__ __align__(16) __half g_o1h[(size_t)N_NODES * C1];    // layer-1 out (fp16)
__device__ __align__(16) __half g_h2h[(size_t)N_NODES * HID];   // o1 @ W2 (fp16)
__device__ __align__(16) float  g_o2[(size_t)N_NODES * HID];    // layer-2 out (fp32)

__device__ __align__(16) float g_ssrc1[N_NODES * HEADS];
__device__ __align__(16) float g_sdst1[N_NODES * HEADS];
__device__ float g_ssrc2[N_NODES];
__device__ float g_sdst2[N_NODES];

__device__ int g_deg[N_NODES];
__device__ int g_cursor[N_NODES];
__device__ int g_rowptr[N_NODES + 1];
__device__ int g_esrc[N_EDGES];
__device__ int g_goff[NG + 1];

// ---------------- fp32 -> fp16 convert (n % 4 == 0) ----------------
__global__ void f2h_kernel(const float* __restrict__ in, __half* __restrict__ out, int n) {
    int i = (blockIdx.x * blockDim.x + threadIdx.x) * 4;
    if (i >= n) return;
    float4 v = *(const float4*)(in + i);
    __half2 a = __floats2half2_rn(v.x, v.y);
    __half2 b = __floats2half2_rn(v.z, v.w);
    uint2 u;
    u.x = *(unsigned int*)&a;
    u.y = *(unsigned int*)&b;
    *(uint2*)(out + i) = u;
}

// ---------------- CSR build ----------------
__global__ void hist_kernel(const int* __restrict__ ei) {
    int e = blockIdx.x * blockDim.x + threadIdx.x;
    if (e >= N_EDGES) return;
    int dst = (e < N_EDGES0) ? ei[N_EDGES0 + e] : (e - N_EDGES0);
    atomicAdd(&g_deg[dst], 1);
}

__global__ void scan_kernel() {
    __shared__ int warpsums[32];
    __shared__ int s_carry;
    int t = threadIdx.x;
    int lane = t & 31, warp = t >> 5;
    if (t == 0) s_carry = 0;
    __syncthreads();
    for (int base = 0; base < N_NODES; base += 4096) {
        int i0 = base + t * 4;
        int v[4];
        #pragma unroll
        for (int j = 0; j < 4; j++) v[j] = (i0 + j < N_NODES) ? g_deg[i0 + j] : 0;
        int s = v[0] + v[1] + v[2] + v[3];
        int x = s;
        #pragma unroll
        for (int o = 1; o < 32; o <<= 1) {
            int y = __shfl_up_sync(0xffffffffu, x, o);
            if (lane >= o) x += y;
        }
        if (lane == 31) warpsums[warp] = x;
        __syncthreads();
        if (warp == 0) {
            int w = warpsums[lane];
            #pragma unroll
            for (int o = 1; o < 32; o <<= 1) {
                int y = __shfl_up_sync(0xffffffffu, w, o);
                if (lane >= o) w += y;
            }
            warpsums[lane] = w;
        }
        __syncthreads();
        int excl = x - s + (warp ? warpsums[warp - 1] : 0) + s_carry;
        int run = excl;
        #pragma unroll
        for (int j = 0; j < 4; j++) {
            if (i0 + j < N_NODES) g_rowptr[i0 + j] = run;
            run += v[j];
        }
        int total = warpsums[31];
        __syncthreads();
        if (t == 0) s_carry += total;
        __syncthreads();
    }
    if (t == 0) g_rowptr[N_NODES] = s_carry;
}

__global__ void scatter_kernel(const int* __restrict__ ei) {
    int e = blockIdx.x * blockDim.x + threadIdx.x;
    if (e >= N_EDGES) return;
    int src, dst;
    if (e < N_EDGES0) { src = ei[e]; dst = ei[N_EDGES0 + e]; }
    else { src = e - N_EDGES0; dst = src; }
    int pos = g_rowptr[dst] + atomicAdd(&g_cursor[dst], 1);
    g_esrc[pos] = src;
}

// ---------------- fp16 HMMA GEMM (optionally fp32 A, converted in staging) ----------------
#define ASTR 40   // half stride of As row (80B)
#define BSTR 72   // half stride of Bs row (144B)

__device__ __forceinline__ unsigned int smem_u32(const void* p) {
    return (unsigned int)__cvta_generic_to_shared(p);
}

__device__ __forceinline__ void ldsm_x4(unsigned int* r, unsigned int addr) {
    asm volatile("ldmatrix.sync.aligned.m8n8.x4.shared.b16 {%0,%1,%2,%3}, [%4];"
                 : "=r"(r[0]), "=r"(r[1]), "=r"(r[2]), "=r"(r[3]) : "r"(addr));
}

__device__ __forceinline__ void ldsm_x4_t(unsigned int* r, unsigned int addr) {
    asm volatile("ldmatrix.sync.aligned.m8n8.x4.trans.shared.b16 {%0,%1,%2,%3}, [%4];"
                 : "=r"(r[0]), "=r"(r[1]), "=r"(r[2]), "=r"(r[3]) : "r"(addr));
}

__device__ __forceinline__ void mma_f16(float* d, const unsigned int* a,
                                        unsigned int b0, unsigned int b1) {
    asm volatile(
        "mma.sync.aligned.m16n8k16.row.col.f32.f16.f16.f32 "
        "{%0,%1,%2,%3}, {%4,%5,%6,%7}, {%8,%9}, {%0,%1,%2,%3};"
        : "+f"(d[0]), "+f"(d[1]), "+f"(d[2]), "+f"(d[3])
        : "r"(a[0]), "r"(a[1]), "r"(a[2]), "r"(a[3]), "r"(b0), "r"(b1));
}

template <bool AF32>
__global__ void __launch_bounds__(256) gemm_hmma_kernel(
    const void* __restrict__ Av, const __half* __restrict__ B, __half* __restrict__ C,
    int M, int Nn, int K)
{
    __shared__ __half As[128 * ASTR];
    __shared__ __half Bs[32 * BSTR];

    int t = threadIdx.x;
    int lane = t & 31, w = t >> 5;
    int wm = w >> 1, wn = w & 1;
    int bm = blockIdx.y * 128, bn = blockIdx.x * 64;

    float acc[2][4][4] = {};

    for (int kk = 0; kk < K; kk += 32) {
        // stage A: 128 rows x 32 halfs; thread -> (row = t>>1, 16-elem chunk = t&1)
        {
            int row = t >> 1, ch = t & 1;
            int gm = bm + row;
            uint4 v0 = make_uint4(0, 0, 0, 0), v1 = v0;
            if (AF32) {
                const float* A = (const float*)Av;
                if (gm < M) {
                    const float4* src = (const float4*)(A + (size_t)gm * K + kk + ch * 16);
                    float4 f0 = src[0], f1 = src[1], f2 = src[2], f3 = src[3];
                    __half2 h0 = __floats2half2_rn(f0.x, f0.y);
                    __half2 h1 = __floats2half2_rn(f0.z, f0.w);
                    __half2 h2 = __floats2half2_rn(f1.x, f1.y);
                    __half2 h3 = __floats2half2_rn(f1.z, f1.w);
                    __half2 h4 = __floats2half2_rn(f2.x, f2.y);
                    __half2 h5 = __floats2half2_rn(f2.z, f2.w);
                    __half2 h6 = __floats2half2_rn(f3.x, f3.y);
                    __half2 h7 = __floats2half2_rn(f3.z, f3.w);
                    v0.x = *(unsigned int*)&h0; v0.y = *(unsigned int*)&h1;
                    v0.z = *(unsigned int*)&h2; v0.w = *(unsigned int*)&h3;
                    v1.x = *(unsigned int*)&h4; v1.y = *(unsigned int*)&h5;
                    v1.z = *(unsigned int*)&h6; v1.w = *(unsigned int*)&h7;
                }
            } else {
                const __half* A = (const __half*)Av;
                if (gm < M) {
                    const uint4* src = (const uint4*)(A + (size_t)gm * K + kk + ch * 16);
                    v0 = src[0]; v1 = src[1];
                }
            }
            *(uint4*)&As[row * ASTR + ch * 16] = v0;
            *(uint4*)&As[row * ASTR + ch * 16 + 8] = v1;
        }
        // stage B
        {
            int row = t >> 3, ch = t & 7;
            uint4 v = *(const uint4*)(B + (size_t)(kk + row) * Nn + bn + ch * 8);
            *(uint4*)&Bs[row * BSTR + ch * 8] = v;
        }
        __syncthreads();
        #pragma unroll
        for (int ks = 0; ks < 2; ks++) {
            unsigned int a[2][4], b[2][4];
            #pragma unroll
            for (int mt = 0; mt < 2; mt++) {
                unsigned int addr = smem_u32(
                    &As[(wm * 32 + mt * 16 + (lane & 15)) * ASTR + ks * 16 + (lane >> 4) * 8]);
                ldsm_x4(a[mt], addr);
            }
            #pragma unroll
            for (int np = 0; np < 2; np++) {
                unsigned int addr = smem_u32(
                    &Bs[(ks * 16 + (lane & 15)) * BSTR + wn * 32 + np * 16 + (lane >> 4) * 8]);
                ldsm_x4_t(b[np], addr);
            }
            #pragma unroll
            for (int mt = 0; mt < 2; mt++)
                #pragma unroll
                for (int nt = 0; nt < 4; nt++)
                    mma_f16(acc[mt][nt], a[mt], b[nt >> 1][(nt & 1) * 2], b[nt >> 1][(nt & 1) * 2 + 1]);
        }
        __syncthreads();
    }
    #pragma unroll
    for (int mt = 0; mt < 2; mt++) {
        int r0 = bm + wm * 32 + mt * 16 + (lane >> 2);
        #pragma unroll
        for (int nt = 0; nt < 4; nt++) {
            int c0 = bn + wn * 32 + nt * 8 + (lane & 3) * 2;
            if (r0 < M)
                *(__half2*)(C + (size_t)r0 * Nn + c0) =
                    __floats2half2_rn(acc[mt][nt][0], acc[mt][nt][1]);
            if (r0 + 8 < M)
                *(__half2*)(C + (size_t)(r0 + 8) * Nn + c0) =
                    __floats2half2_rn(acc[mt][nt][2], acc[mt][nt][3]);
        }
    }
}

// ---------------- attention scores ----------------
__global__ void scores1_kernel(const float* __restrict__ asrc, const float* __restrict__ adst) {
    int gw = (blockIdx.x * blockDim.x + threadIdx.x) >> 5;
    int lane = threadIdx.x & 31;
    if (gw >= N_NODES * HEADS) return;
    int n = gw >> 2, h = gw & 3;
    const __half* hp = g_h1h + (size_t)n * C1 + h * HID;
    float v0 = __half2float(hp[lane]), v1 = __half2float(hp[lane + 32]);
    float s1 = v0 * asrc[h * HID + lane] + v1 * asrc[h * HID + lane + 32];
    float s2 = v0 * adst[h * HID + lane] + v1 * adst[h * HID + lane + 32];
    #pragma unroll
    for (int o = 16; o; o >>= 1) {
        s1 += __shfl_down_sync(0xffffffffu, s1, o);
        s2 += __shfl_down_sync(0xffffffffu, s2, o);
    }
    if (lane == 0) {
        g_ssrc1[n * 4 + h] = s1;
        g_sdst1[n * 4 + h] = s2;
    }
}

__global__ void scores2_kernel(const float* __restrict__ asrc, const float* __restrict__ adst) {
    int gw = (blockIdx.x * blockDim.x + threadIdx.x) >> 5;
    int lane = threadIdx.x & 31;
    if (gw >= N_NODES) return;
    const __half* hp = g_h2h + (size_t)gw * HID;
    float v0 = __half2float(hp[lane]), v1 = __half2float(hp[lane + 32]);
    float s1 = v0 * asrc[lane] + v1 * asrc[lane + 32];
    float s2 = v0 * adst[lane] + v1 * adst[lane + 32];
    #pragma unroll
    for (int o = 16; o; o >>= 1) {
        s1 += __shfl_down_sync(0xffffffffu, s1, o);
        s2 += __shfl_down_sync(0xffffffffu, s2, o);
    }
    if (lane == 0) {
        g_ssrc2[gw] = s1;
        g_sdst2[gw] = s2;
    }
}

// ---------------- helpers ----------------
__device__ __forceinline__ float lrelu_exp(float s) {
    s = s > 0.f ? s : SLOPE * s;
    return __expf(s);
}

__device__ __forceinline__ void acc8(float* acc, float w, const uint4& v) {
    float2 f0 = __half22float2(*(__half2*)&v.x);
    float2 f1 = __half22float2(*(__half2*)&v.y);
    float2 f2 = __half22float2(*(__half2*)&v.z);
    float2 f3 = __half22float2(*(__half2*)&v.w);
    acc[0] += w * f0.x; acc[1] += w * f0.y;
    acc[2] += w * f1.x; acc[3] += w * f1.y;
    acc[4] += w * f2.x; acc[5] += w * f2.y;
    acc[6] += w * f3.x; acc[7] += w * f3.y;
}

// ---------------- aggregation layer 1: warp per node, no smem/syncs ----------------
// lane owns 8 channels (16B fp16 gather per edge); head = lane>>3.
__global__ void __launch_bounds__(256) aggregate1_kernel(const float* __restrict__ b1) {
    int n = (blockIdx.x * blockDim.x + threadIdx.x) >> 5;
    if (n >= N_NODES) return;
    int l = threadIdx.x & 31;
    int h = l >> 3;
    int r0 = g_rowptr[n], r1 = g_rowptr[n + 1];
    float dvh = g_sdst1[n * 4 + h];

    float acc[8] = {};
    float den = 0.f;
    const __half* hb = g_h1h + l * 8;

    int e = r0;
    for (; e + 3 < r1; e += 4) {
        int s0 = g_esrc[e], s1 = g_esrc[e + 1], s2 = g_esrc[e + 2], s3 = g_esrc[e + 3];
        float w0 = lrelu_exp(g_ssrc1[s0 * 4 + h] + dvh);
        float w1 = lrelu_exp(g_ssrc1[s1 * 4 + h] + dvh);
        float w2 = lrelu_exp(g_ssrc1[s2 * 4 + h] + dvh);
        float w3 = lrelu_exp(g_ssrc1[s3 * 4 + h] + dvh);
        uint4 v0 = *(const uint4*)(hb + (size_t)s0 * C1);
        uint4 v1 = *(const uint4*)(hb + (size_t)s1 * C1);
        uint4 v2 = *(const uint4*)(hb + (size_t)s2 * C1);
        uint4 v3 = *(const uint4*)(hb + (size_t)s3 * C1);
        acc8(acc, w0, v0); acc8(acc, w1, v1);
        acc8(acc, w2, v2); acc8(acc, w3, v3);
        den += (w0 + w1) + (w2 + w3);
    }
    for (; e < r1; e++) {
        int s0 = g_esrc[e];
        float w0 = lrelu_exp(g_ssrc1[s0 * 4 + h] + dvh);
        uint4 v0 = *(const uint4*)(hb + (size_t)s0 * C1);
        acc8(acc, w0, v0);
        den += w0;
    }

    float inv = 1.f / (den + 1e-16f);
    float4 bb0 = *(const float4*)(b1 + l * 8);
    float4 bb1 = *(const float4*)(b1 + l * 8 + 4);
    float o[8];
    o[0] = acc[0] * inv + bb0.x; o[1] = acc[1] * inv + bb0.y;
    o[2] = acc[2] * inv + bb0.z; o[3] = acc[3] * inv + bb0.w;
    o[4] = acc[4] * inv + bb1.x; o[5] = acc[5] * inv + bb1.y;
    o[6] = acc[6] * inv + bb1.z; o[7] = acc[7] * inv + bb1.w;
    #pragma unroll
    for (int j = 0; j < 8; j++) o[j] = o[j] > 0.f ? o[j] : expm1f(o[j]);
    __half2 p0 = __floats2half2_rn(o[0], o[1]);
    __half2 p1 = __floats2half2_rn(o[2], o[3]);
    __half2 p2 = __floats2half2_rn(o[4], o[5]);
    __half2 p3 = __floats2half2_rn(o[6], o[7]);
    uint4 u;
    u.x = *(unsigned int*)&p0; u.y = *(unsigned int*)&p1;
    u.z = *(unsigned int*)&p2; u.w = *(unsigned int*)&p3;
    *(uint4*)(g_o1h + (size_t)n * C1 + l * 8) = u;
}

// ---------------- aggregation layer 2: warp per node ----------------
// lane owns 2 channels (4B fp16 gather per edge); single head.
__global__ void __launch_bounds__(256) aggregate2_kernel(const float* __restrict__ b2) {
    int n = (blockIdx.x * blockDim.x + threadIdx.x) >> 5;
    if (n >= N_NODES) return;
    int l = threadIdx.x & 31;
    int r0 = g_rowptr[n], r1 = g_rowptr[n + 1];
    float sd = g_sdst2[n];

    float a0 = 0.f, a1 = 0.f;
    float den = 0.f;
    const __half* hb = g_h2h + l * 2;

    int e = r0;
    for (; e + 3 < r1; e += 4) {
        int s0 = g_esrc[e], s1 = g_esrc[e + 1], s2 = g_esrc[e + 2], s3 = g_esrc[e + 3];
        float w0 = lrelu_exp(g_ssrc2[s0] + sd);
        float w1 = lrelu_exp(g_ssrc2[s1] + sd);
        float w2 = lrelu_exp(g_ssrc2[s2] + sd);
        float w3 = lrelu_exp(g_ssrc2[s3] + sd);
        __half2 v0 = *(const __half2*)(hb + (size_t)s0 * HID);
        __half2 v1 = *(const __half2*)(hb + (size_t)s1 * HID);
        __half2 v2 = *(const __half2*)(hb + (size_t)s2 * HID);
        __half2 v3 = *(const __half2*)(hb + (size_t)s3 * HID);
        float2 f0 = __half22float2(v0), f1 = __half22float2(v1);
        float2 f2 = __half22float2(v2), f3 = __half22float2(v3);
        a0 += w0 * f0.x + w1 * f1.x + w2 * f2.x + w3 * f3.x;
        a1 += w0 * f0.y + w1 * f1.y + w2 * f2.y + w3 * f3.y;
        den += (w0 + w1) + (w2 + w3);
    }
    for (; e < r1; e++) {
        int s0 = g_esrc[e];
        float w0 = lrelu_exp(g_ssrc2[s0] + sd);
        float2 f0 = __half22float2(*(const __half2*)(hb + (size_t)s0 * HID));
        a0 += w0 * f0.x; a1 += w0 * f0.y;
        den += w0;
    }

    float inv = 1.f / (den + 1e-16f);
    float o0 = a0 * inv + b2[l * 2];
    float o1 = a1 * inv + b2[l * 2 + 1];
    o0 = o0 > 0.f ? o0 : expm1f(o0);
    o1 = o1 > 0.f ? o1 : expm1f(o1);
    *(float2*)(g_o2 + (size_t)n * HID + l * 2) = make_float2(o0, o1);
}

// ---------------- graph offsets ----------------
__global__ void graph_offsets_kernel(const int* __restrict__ batch) {
    int g = blockIdx.x * blockDim.x + threadIdx.x;
    if (g > NG) return;
    if (g == NG) { g_goff[NG] = N_NODES; return; }
    int lo = 0, hi = N_NODES;
    while (lo < hi) {
        int mid = (lo + hi) >> 1;
        if (batch[mid] < g) lo = mid + 1; else hi = mid;
    }
    g_goff[g] = lo;
}

// ---------------- pool + fc + log_softmax ----------------
__global__ void __launch_bounds__(256) pool_fc_kernel(const float* __restrict__ fcw,
                                                      const float* __restrict__ fcb,
                                                      float* __restrict__ out) {
    int g = blockIdx.x;
    int t = threadIdx.x;
    int c = t & 63, rep = t >> 6;
    int s = g_goff[g], e = g_goff[g + 1];
    float sum = 0.f;
    for (int i = s + rep; i < e; i += 4)
        sum += g_o2[(size_t)i * HID + c];
    __shared__ float red[256];
    red[t] = sum;
    __syncthreads();
    if (t < 64) {
        float tot = red[t] + red[t + 64] + red[t + 128] + red[t + 192];
        float cnt = (float)max(e - s, 1);
        float pooled = tot / cnt;
        red[t]      = pooled * fcw[c * 2 + 0];
        red[t + 64] = pooled * fcw[c * 2 + 1];
    }
    __syncthreads();
    if (t < 2) {
        float l = fcb[t];
        for (int i = 0; i < 64; i++) l += red[t * 64 + i];
        red[128 + t] = l;
    }
    __syncthreads();
    if (t == 0) {
        float l0 = red[128], l1 = red[129];
        float m = fmaxf(l0, l1);
        float lse = m + logf(__expf(l0 - m) + __expf(l1 - m));
        out[g * 2 + 0] = l0 - lse;
        out[g * 2 + 1] = l1 - lse;
    }
}

// ---------------- launch ----------------
extern "C" void kernel_launch(void* const* d_in, const int* in_sizes, int n_in,
                              void* d_out, int out_size) {
    const float* x    = (const float*)d_in[0];
    const int*   ei   = (const int*)d_in[1];
    const int*   bat  = (const int*)d_in[2];
    const float* W1   = (const float*)d_in[3];
    const float* as1  = (const float*)d_in[4];
    const float* ad1  = (const float*)d_in[5];
    const float* b1   = (const float*)d_in[6];
    const float* W2   = (const float*)d_in[7];
    const float* as2  = (const float*)d_in[8];
    const float* ad2  = (const float*)d_in[9];
    const float* b2   = (const float*)d_in[10];
    const float* fcw  = (const float*)d_in[11];
    const float* fcb  = (const float*)d_in[12];
    float* out = (float*)d_out;

    __half* w1hp; cudaGetSymbolAddress((void**)&w1hp, g_W1h);
    __half* w2hp; cudaGetSymbolAddress((void**)&w2hp, g_W2h);
    __half* h1p;  cudaGetSymbolAddress((void**)&h1p,  g_h1h);
    __half* o1p;  cudaGetSymbolAddress((void**)&o1p,  g_o1h);
    __half* h2p;  cudaGetSymbolAddress((void**)&h2p,  g_h2h);
    int* degp;    cudaGetSymbolAddress((void**)&degp, g_deg);
    int* curp;    cudaGetSymbolAddress((void**)&curp, g_cursor);

    // side stream + events for fork/join inside graph capture
    cudaStream_t side;
    cudaStreamCreateWithFlags(&side, cudaStreamNonBlocking);
    cudaEvent_t evF, evJ;
    cudaEventCreateWithFlags(&evF, cudaEventDisableTiming);
    cudaEventCreateWithFlags(&evJ, cudaEventDisableTiming);

    // fork: CSR build on side stream
    cudaEventRecord(evF, 0);
    cudaStreamWaitEvent(side, evF, 0);
    cudaMemsetAsync(degp, 0, N_NODES * sizeof(int), side);
    cudaMemsetAsync(curp, 0, N_NODES * sizeof(int), side);
    hist_kernel<<<(N_EDGES + 255) / 256, 256, 0, side>>>(ei);
    scan_kernel<<<1, 1024, 0, side>>>();
    scatter_kernel<<<(N_EDGES + 255) / 256, 256, 0, side>>>(ei);
    cudaEventRecord(evJ, side);

    // main: weight converts + gemm1 (A converted in-kernel) + scores1
    f2h_kernel<<<(F_IN * C1 / 4 + 255) / 256, 256>>>(W1, w1hp, F_IN * C1);
    f2h_kernel<<<(C1 * HID / 4 + 255) / 256, 256>>>(W2, w2hp, C1 * HID);
    graph_offsets_kernel<<<1, 128>>>(bat);

    dim3 g1(C1 / 64, (N_NODES + 127) / 128);
    gemm_hmma_kernel<true><<<g1, 256>>>(x, w1hp, h1p, N_NODES, C1, F_IN);
    scores1_kernel<<<(N_NODES * HEADS * 32 + 255) / 256, 256>>>(as1, ad1);

    // join: aggregate1 needs CSR + scores
    cudaStreamWaitEvent(0, evJ, 0);
    aggregate1_kernel<<<(N_NODES * 32 + 255) / 256, 256>>>(b1);

    // layer 2
    dim3 g2(HID / 64, (N_NODES + 127) / 128);
    gemm_hmma_kernel<false><<<g2, 256>>>(o1p, w2hp, h2p, N_NODES, HID, C1);
    scores2_kernel<<<(N_NODES * 32 + 255) / 256, 256>>>(as2, ad2);
    aggregate2_kernel<<<(N_NODES * 32 + 255) / 256, 256>>>(b2);

    // pool + classifier
    pool_fc_kernel<<<NG, 256>>>(fcw, fcb, out);
}

// round 9
// speedup vs baseline: 2.7342x; 1.1386x over previous
#include <cuda_runtime.h>
#include <cuda_fp16.h>
#include <cstdint>
#include <math.h>

// ---------------- problem constants ----------------
#define N_NODES   50000
#define N_EDGES0  800000
#define N_EDGES   850000      // + self loops
#define F_IN      128
#define HID       64
#define HEADS     4
#define C1        256         // HEADS*HID
#define NG        64
#define SLOPE     0.2f

// ---------------- scratch (device globals) ----------------
__device__ __align__(16) __half g_W1h[F_IN * C1];
__device__ __align__(16) __half g_W2h[C1 * HID];
__device__ __align__(16) __half g_h1h[(size_t)N_NODES * C1];    // x @ W1 (fp16)
__device__ __align__(16) __half g_o1h[(size_t)N_NODES * C1];    // layer-1 out (fp16)
__device__ __align__(16) __half g_h2h[(size_t)N_NODES * HID];   // o1 @ W2 (fp16)
__device__ __align__(16) float  g_o2[(size_t)N_NODES * HID];    // layer-2 out (fp32)

__device__ __align__(16) float g_ssrc1[N_NODES * HEADS];
__device__ __align__(16) float g_sdst1[N_NODES * HEADS];
__device__ float g_ssrc2[N_NODES];
__device__ float g_sdst2[N_NODES];

__device__ int g_deg[N_NODES];
__device__ int g_cursor[N_NODES];
__device__ int g_rowptr[N_NODES + 1];
__device__ int g_esrc[N_EDGES];
__device__ int g_goff[NG + 1];

// ---------------- fp32 -> fp16 convert (n % 4 == 0) ----------------
__global__ void f2h_kernel(const float* __restrict__ in, __half* __restrict__ out, int n) {
    int i = (blockIdx.x * blockDim.x + threadIdx.x) * 4;
    if (i >= n) return;
    float4 v = *(const float4*)(in + i);
    __half2 a = __floats2half2_rn(v.x, v.y);
    __half2 b = __floats2half2_rn(v.z, v.w);
    uint2 u;
    u.x = *(unsigned int*)&a;
    u.y = *(unsigned int*)&b;
    *(uint2*)(out + i) = u;
}

// ---------------- CSR build ----------------
__global__ void hist_kernel(const int* __restrict__ ei) {
    int e = blockIdx.x * blockDim.x + threadIdx.x;
    if (e >= N_EDGES) return;
    int dst = (e < N_EDGES0) ? ei[N_EDGES0 + e] : (e - N_EDGES0);
    atomicAdd(&g_deg[dst], 1);
}

__global__ void scan_kernel() {
    __shared__ int warpsums[32];
    __shared__ int s_carry;
    int t = threadIdx.x;
    int lane = t & 31, warp = t >> 5;
    if (t == 0) s_carry = 0;
    __syncthreads();
    for (int base = 0; base < N_NODES; base += 4096) {
        int i0 = base + t * 4;
        int v[4];
        #pragma unroll
        for (int j = 0; j < 4; j++) v[j] = (i0 + j < N_NODES) ? g_deg[i0 + j] : 0;
        int s = v[0] + v[1] + v[2] + v[3];
        int x = s;
        #pragma unroll
        for (int o = 1; o < 32; o <<= 1) {
            int y = __shfl_up_sync(0xffffffffu, x, o);
            if (lane >= o) x += y;
        }
        if (lane == 31) warpsums[warp] = x;
        __syncthreads();
        if (warp == 0) {
            int w = warpsums[lane];
            #pragma unroll
            for (int o = 1; o < 32; o <<= 1) {
                int y = __shfl_up_sync(0xffffffffu, w, o);
                if (lane >= o) w += y;
            }
            warpsums[lane] = w;
        }
        __syncthreads();
        int excl = x - s + (warp ? warpsums[warp - 1] : 0) + s_carry;
        int run = excl;
        #pragma unroll
        for (int j = 0; j < 4; j++) {
            if (i0 + j < N_NODES) g_rowptr[i0 + j] = run;
            run += v[j];
        }
        int total = warpsums[31];
        __syncthreads();
        if (t == 0) s_carry += total;
        __syncthreads();
    }
    if (t == 0) g_rowptr[N_NODES] = s_carry;
}

__global__ void scatter_kernel(const int* __restrict__ ei) {
    int e = blockIdx.x * blockDim.x + threadIdx.x;
    if (e >= N_EDGES) return;
    int src, dst;
    if (e < N_EDGES0) { src = ei[e]; dst = ei[N_EDGES0 + e]; }
    else { src = e - N_EDGES0; dst = src; }
    int pos = g_rowptr[dst] + atomicAdd(&g_cursor[dst], 1);
    g_esrc[pos] = src;
}

// ---------------- fp16 HMMA GEMM + fused attention scores ----------------
// C_fp16[M,Nn] = A[M,K] @ B_fp16[K,Nn]; A fp32 (converted in staging) or fp16.
// BN == 64 == head width, so head = blockIdx.x.
// ssrc[m*heads+head] = sum_c C[m, head*64+c]*asrc[head*64+c]; same for sdst.
#define ASTR 40   // half stride of As row (80B)
#define BSTR 72   // half stride of Bs row (144B)

__device__ __forceinline__ unsigned int smem_u32(const void* p) {
    return (unsigned int)__cvta_generic_to_shared(p);
}

__device__ __forceinline__ void ldsm_x4(unsigned int* r, unsigned int addr) {
    asm volatile("ldmatrix.sync.aligned.m8n8.x4.shared.b16 {%0,%1,%2,%3}, [%4];"
                 : "=r"(r[0]), "=r"(r[1]), "=r"(r[2]), "=r"(r[3]) : "r"(addr));
}

__device__ __forceinline__ void ldsm_x4_t(unsigned int* r, unsigned int addr) {
    asm volatile("ldmatrix.sync.aligned.m8n8.x4.trans.shared.b16 {%0,%1,%2,%3}, [%4];"
                 : "=r"(r[0]), "=r"(r[1]), "=r"(r[2]), "=r"(r[3]) : "r"(addr));
}

__device__ __forceinline__ void mma_f16(float* d, const unsigned int* a,
                                        unsigned int b0, unsigned int b1) {
    asm volatile(
        "mma.sync.aligned.m16n8k16.row.col.f32.f16.f16.f32 "
        "{%0,%1,%2,%3}, {%4,%5,%6,%7}, {%8,%9}, {%0,%1,%2,%3};"
        : "+f"(d[0]), "+f"(d[1]), "+f"(d[2]), "+f"(d[3])
        : "r"(a[0]), "r"(a[1]), "r"(a[2]), "r"(a[3]), "r"(b0), "r"(b1));
}

template <bool AF32>
__global__ void __launch_bounds__(256) gemm_gat_kernel(
    const void* __restrict__ Av, const __half* __restrict__ B, __half* __restrict__ C,
    int M, int Nn, int K,
    const float* __restrict__ asrc, const float* __restrict__ adst,
    float* __restrict__ ssrc, float* __restrict__ sdst, int heads)
{
    __shared__ __half As[128 * ASTR];
    __shared__ __half Bs[32 * BSTR];
    __shared__ float sSm[2][128];
    __shared__ float sDm[2][128];

    int t = threadIdx.x;
    int lane = t & 31, w = t >> 5;
    int wm = w >> 1, wn = w & 1;
    int bm = blockIdx.y * 128, bn = blockIdx.x * 64;
    int head = blockIdx.x;

    float acc[2][4][4] = {};

    for (int kk = 0; kk < K; kk += 32) {
        // stage A
        {
            int row = t >> 1, ch = t & 1;
            int gm = bm + row;
            uint4 v0 = make_uint4(0, 0, 0, 0), v1 = v0;
            if (AF32) {
                const float* A = (const float*)Av;
                if (gm < M) {
                    const float4* src = (const float4*)(A + (size_t)gm * K + kk + ch * 16);
                    float4 f0 = src[0], f1 = src[1], f2 = src[2], f3 = src[3];
                    __half2 h0 = __floats2half2_rn(f0.x, f0.y);
                    __half2 h1 = __floats2half2_rn(f0.z, f0.w);
                    __half2 h2 = __floats2half2_rn(f1.x, f1.y);
                    __half2 h3 = __floats2half2_rn(f1.z, f1.w);
                    __half2 h4 = __floats2half2_rn(f2.x, f2.y);
                    __half2 h5 = __floats2half2_rn(f2.z, f2.w);
                    __half2 h6 = __floats2half2_rn(f3.x, f3.y);
                    __half2 h7 = __floats2half2_rn(f3.z, f3.w);
                    v0.x = *(unsigned int*)&h0; v0.y = *(unsigned int*)&h1;
                    v0.z = *(unsigned int*)&h2; v0.w = *(unsigned int*)&h3;
                    v1.x = *(unsigned int*)&h4; v1.y = *(unsigned int*)&h5;
                    v1.z = *(unsigned int*)&h6; v1.w = *(unsigned int*)&h7;
                }
            } else {
                const __half* A = (const __half*)Av;
                if (gm < M) {
                    const uint4* src = (const uint4*)(A + (size_t)gm * K + kk + ch * 16);
                    v0 = src[0]; v1 = src[1];
                }
            }
            *(uint4*)&As[row * ASTR + ch * 16] = v0;
            *(uint4*)&As[row * ASTR + ch * 16 + 8] = v1;
        }
        // stage B
        {
            int row = t >> 3, ch = t & 7;
            uint4 v = *(const uint4*)(B + (size_t)(kk + row) * Nn + bn + ch * 8);
            *(uint4*)&Bs[row * BSTR + ch * 8] = v;
        }
        __syncthreads();
        #pragma unroll
        for (int ks = 0; ks < 2; ks++) {
            unsigned int a[2][4], b[2][4];
            #pragma unroll
            for (int mt = 0; mt < 2; mt++) {
                unsigned int addr = smem_u32(
                    &As[(wm * 32 + mt * 16 + (lane & 15)) * ASTR + ks * 16 + (lane >> 4) * 8]);
                ldsm_x4(a[mt], addr);
            }
            #pragma unroll
            for (int np = 0; np < 2; np++) {
                unsigned int addr = smem_u32(
                    &Bs[(ks * 16 + (lane & 15)) * BSTR + wn * 32 + np * 16 + (lane >> 4) * 8]);
                ldsm_x4_t(b[np], addr);
            }
            #pragma unroll
            for (int mt = 0; mt < 2; mt++)
                #pragma unroll
                for (int nt = 0; nt < 4; nt++)
                    mma_f16(acc[mt][nt], a[mt], b[nt >> 1][(nt & 1) * 2], b[nt >> 1][(nt & 1) * 2 + 1]);
        }
        __syncthreads();
    }

    // ---- fused attention scores ----
    {
        float av[4][2], dv[4][2];
        #pragma unroll
        for (int nt = 0; nt < 4; nt++) {
            int c = head * 64 + wn * 32 + nt * 8 + (lane & 3) * 2;
            av[nt][0] = asrc[c]; av[nt][1] = asrc[c + 1];
            dv[nt][0] = adst[c]; dv[nt][1] = adst[c + 1];
        }
        #pragma unroll
        for (int mt = 0; mt < 2; mt++) {
            #pragma unroll
            for (int hf = 0; hf < 2; hf++) {
                float sS = 0.f, sD = 0.f;
                #pragma unroll
                for (int nt = 0; nt < 4; nt++) {
                    sS += acc[mt][nt][hf * 2 + 0] * av[nt][0]
                        + acc[mt][nt][hf * 2 + 1] * av[nt][1];
                    sD += acc[mt][nt][hf * 2 + 0] * dv[nt][0]
                        + acc[mt][nt][hf * 2 + 1] * dv[nt][1];
                }
                sS += __shfl_xor_sync(0xffffffffu, sS, 1);
                sS += __shfl_xor_sync(0xffffffffu, sS, 2);
                sD += __shfl_xor_sync(0xffffffffu, sD, 1);
                sD += __shfl_xor_sync(0xffffffffu, sD, 2);
                if ((lane & 3) == 0) {
                    int rowl = wm * 32 + mt * 16 + hf * 8 + (lane >> 2);
                    sSm[wn][rowl] = sS;
                    sDm[wn][rowl] = sD;
                }
            }
        }
        __syncthreads();
        if (t < 128) {
            int gm = bm + t;
            if (gm < M) {
                ssrc[gm * heads + head] = sSm[0][t] + sSm[1][t];
                sdst[gm * heads + head] = sDm[0][t] + sDm[1][t];
            }
        }
    }

    // ---- C stores ----
    #pragma unroll
    for (int mt = 0; mt < 2; mt++) {
        int r0 = bm + wm * 32 + mt * 16 + (lane >> 2);
        #pragma unroll
        for (int nt = 0; nt < 4; nt++) {
            int c0 = bn + wn * 32 + nt * 8 + (lane & 3) * 2;
            if (r0 < M)
                *(__half2*)(C + (size_t)r0 * Nn + c0) =
                    __floats2half2_rn(acc[mt][nt][0], acc[mt][nt][1]);
            if (r0 + 8 < M)
                *(__half2*)(C + (size_t)(r0 + 8) * Nn + c0) =
                    __floats2half2_rn(acc[mt][nt][2], acc[mt][nt][3]);
        }
    }
}

// ---------------- helpers ----------------
__device__ __forceinline__ float lrelu_exp(float s) {
    s = s > 0.f ? s : SLOPE * s;
    return __expf(s);
}

__device__ __forceinline__ void acc8(float* acc, float w, const uint4& v) {
    float2 f0 = __half22float2(*(__half2*)&v.x);
    float2 f1 = __half22float2(*(__half2*)&v.y);
    float2 f2 = __half22float2(*(__half2*)&v.z);
    float2 f3 = __half22float2(*(__half2*)&v.w);
    acc[0] += w * f0.x; acc[1] += w * f0.y;
    acc[2] += w * f1.x; acc[3] += w * f1.y;
    acc[4] += w * f2.x; acc[5] += w * f2.y;
    acc[6] += w * f3.x; acc[7] += w * f3.y;
}

// ---------------- aggregation layer 1: warp per node ----------------
__global__ void __launch_bounds__(256) aggregate1_kernel(const float* __restrict__ b1) {
    int n = (blockIdx.x * blockDim.x + threadIdx.x) >> 5;
    if (n >= N_NODES) return;
    int l = threadIdx.x & 31;
    int h = l >> 3;
    int r0 = g_rowptr[n], r1 = g_rowptr[n + 1];
    float dvh = g_sdst1[n * 4 + h];

    float acc[8] = {};
    float den = 0.f;
    const __half* hb = g_h1h + l * 8;

    int e = r0;
    for (; e + 3 < r1; e += 4) {
        int s0 = g_esrc[e], s1 = g_esrc[e + 1], s2 = g_esrc[e + 2], s3 = g_esrc[e + 3];
        float w0 = lrelu_exp(g_ssrc1[s0 * 4 + h] + dvh);
        float w1 = lrelu_exp(g_ssrc1[s1 * 4 + h] + dvh);
        float w2 = lrelu_exp(g_ssrc1[s2 * 4 + h] + dvh);
        float w3 = lrelu_exp(g_ssrc1[s3 * 4 + h] + dvh);
        uint4 v0 = *(const uint4*)(hb + (size_t)s0 * C1);
        uint4 v1 = *(const uint4*)(hb + (size_t)s1 * C1);
        uint4 v2 = *(const uint4*)(hb + (size_t)s2 * C1);
        uint4 v3 = *(const uint4*)(hb + (size_t)s3 * C1);
        acc8(acc, w0, v0); acc8(acc, w1, v1);
        acc8(acc, w2, v2); acc8(acc, w3, v3);
        den += (w0 + w1) + (w2 + w3);
    }
    for (; e < r1; e++) {
        int s0 = g_esrc[e];
        float w0 = lrelu_exp(g_ssrc1[s0 * 4 + h] + dvh);
        uint4 v0 = *(const uint4*)(hb + (size_t)s0 * C1);
        acc8(acc, w0, v0);
        den += w0;
    }

    float inv = 1.f / (den + 1e-16f);
    float4 bb0 = *(const float4*)(b1 + l * 8);
    float4 bb1 = *(const float4*)(b1 + l * 8 + 4);
    float o[8];
    o[0] = acc[0] * inv + bb0.x; o[1] = acc[1] * inv + bb0.y;
    o[2] = acc[2] * inv + bb0.z; o[3] = acc[3] * inv + bb0.w;
    o[4] = acc[4] * inv + bb1.x; o[5] = acc[5] * inv + bb1.y;
    o[6] = acc[6] * inv + bb1.z; o[7] = acc[7] * inv + bb1.w;
    #pragma unroll
    for (int j = 0; j < 8; j++) o[j] = o[j] > 0.f ? o[j] : expm1f(o[j]);
    __half2 p0 = __floats2half2_rn(o[0], o[1]);
    __half2 p1 = __floats2half2_rn(o[2], o[3]);
    __half2 p2 = __floats2half2_rn(o[4], o[5]);
    __half2 p3 = __floats2half2_rn(o[6], o[7]);
    uint4 u;
    u.x = *(unsigned int*)&p0; u.y = *(unsigned int*)&p1;
    u.z = *(unsigned int*)&p2; u.w = *(unsigned int*)&p3;
    *(uint4*)(g_o1h + (size_t)n * C1 + l * 8) = u;
}

// ---------------- aggregation layer 2: warp per node ----------------
__global__ void __launch_bounds__(256) aggregate2_kernel(const float* __restrict__ b2) {
    int n = (blockIdx.x * blockDim.x + threadIdx.x) >> 5;
    if (n >= N_NODES) return;
    int l = threadIdx.x & 31;
    int r0 = g_rowptr[n], r1 = g_rowptr[n + 1];
    float sd = g_sdst2[n];

    float a0 = 0.f, a1 = 0.f;
    float den = 0.f;
    const __half* hb = g_h2h + l * 2;

    int e = r0;
    for (; e + 3 < r1; e += 4) {
        int s0 = g_esrc[e], s1 = g_esrc[e + 1], s2 = g_esrc[e + 2], s3 = g_esrc[e + 3];
        float w0 = lrelu_exp(g_ssrc2[s0] + sd);
        float w1 = lrelu_exp(g_ssrc2[s1] + sd);
        float w2 = lrelu_exp(g_ssrc2[s2] + sd);
        float w3 = lrelu_exp(g_ssrc2[s3] + sd);
        __half2 v0 = *(const __half2*)(hb + (size_t)s0 * HID);
        __half2 v1 = *(const __half2*)(hb + (size_t)s1 * HID);
        __half2 v2 = *(const __half2*)(hb + (size_t)s2 * HID);
        __half2 v3 = *(const __half2*)(hb + (size_t)s3 * HID);
        float2 f0 = __half22float2(v0), f1 = __half22float2(v1);
        float2 f2 = __half22float2(v2), f3 = __half22float2(v3);
        a0 += w0 * f0.x + w1 * f1.x + w2 * f2.x + w3 * f3.x;
        a1 += w0 * f0.y + w1 * f1.y + w2 * f2.y + w3 * f3.y;
        den += (w0 + w1) + (w2 + w3);
    }
    for (; e < r1; e++) {
        int s0 = g_esrc[e];
        float w0 = lrelu_exp(g_ssrc2[s0] + sd);
        float2 f0 = __half22float2(*(const __half2*)(hb + (size_t)s0 * HID));
        a0 += w0 * f0.x; a1 += w0 * f0.y;
        den += w0;
    }

    float inv = 1.f / (den + 1e-16f);
    float o0 = a0 * inv + b2[l * 2];
    float o1 = a1 * inv + b2[l * 2 + 1];
    o0 = o0 > 0.f ? o0 : expm1f(o0);
    o1 = o1 > 0.f ? o1 : expm1f(o1);
    *(float2*)(g_o2 + (size_t)n * HID + l * 2) = make_float2(o0, o1);
}

// ---------------- graph offsets ----------------
__global__ void graph_offsets_kernel(const int* __restrict__ batch) {
    int g = blockIdx.x * blockDim.x + threadIdx.x;
    if (g > NG) return;
    if (g == NG) { g_goff[NG] = N_NODES; return; }
    int lo = 0, hi = N_NODES;
    while (lo < hi) {
        int mid = (lo + hi) >> 1;
        if (batch[mid] < g) lo = mid + 1; else hi = mid;
    }
    g_goff[g] = lo;
}

// ---------------- pool + fc + log_softmax ----------------
__global__ void __launch_bounds__(256) pool_fc_kernel(const float* __restrict__ fcw,
                                                      const float* __restrict__ fcb,
                                                      float* __restrict__ out) {
    int g = blockIdx.x;
    int t = threadIdx.x;
    int c = t & 63, rep = t >> 6;
    int s = g_goff[g], e = g_goff[g + 1];
    float sum = 0.f;
    for (int i = s + rep; i < e; i += 4)
        sum += g_o2[(size_t)i * HID + c];
    __shared__ float red[256];
    red[t] = sum;
    __syncthreads();
    if (t < 64) {
        float tot = red[t] + red[t + 64] + red[t + 128] + red[t + 192];
        float cnt = (float)max(e - s, 1);
        float pooled = tot / cnt;
        red[t]      = pooled * fcw[c * 2 + 0];
        red[t + 64] = pooled * fcw[c * 2 + 1];
    }
    __syncthreads();
    if (t < 2) {
        float l = fcb[t];
        for (int i = 0; i < 64; i++) l += red[t * 64 + i];
        red[128 + t] = l;
    }
    __syncthreads();
    if (t == 0) {
        float l0 = red[128], l1 = red[129];
        float m = fmaxf(l0, l1);
        float lse = m + logf(__expf(l0 - m) + __expf(l1 - m));
        out[g * 2 + 0] = l0 - lse;
        out[g * 2 + 1] = l1 - lse;
    }
}

// ---------------- launch ----------------
extern "C" void kernel_launch(void* const* d_in, const int* in_sizes, int n_in,
                              void* d_out, int out_size) {
    const float* x    = (const float*)d_in[0];
    const int*   ei   = (const int*)d_in[1];
    const int*   bat  = (const int*)d_in[2];
    const float* W1   = (const float*)d_in[3];
    const float* as1  = (const float*)d_in[4];
    const float* ad1  = (const float*)d_in[5];
    const float* b1   = (const float*)d_in[6];
    const float* W2   = (const float*)d_in[7];
    const float* as2  = (const float*)d_in[8];
    const float* ad2  = (const float*)d_in[9];
    const float* b2   = (const float*)d_in[10];
    const float* fcw  = (const float*)d_in[11];
    const float* fcb  = (const float*)d_in[12];
    float* out = (float*)d_out;

    __half* w1hp; cudaGetSymbolAddress((void**)&w1hp, g_W1h);
    __half* w2hp; cudaGetSymbolAddress((void**)&w2hp, g_W2h);
    __half* h1p;  cudaGetSymbolAddress((void**)&h1p,  g_h1h);
    __half* o1p;  cudaGetSymbolAddress((void**)&o1p,  g_o1h);
    __half* h2p;  cudaGetSymbolAddress((void**)&h2p,  g_h2h);
    float* s1p;   cudaGetSymbolAddress((void**)&s1p,  g_ssrc1);
    float* d1p;   cudaGetSymbolAddress((void**)&d1p,  g_sdst1);
    float* s2p;   cudaGetSymbolAddress((void**)&s2p,  g_ssrc2);
    float* d2p;   cudaGetSymbolAddress((void**)&d2p,  g_sdst2);
    int* degp;    cudaGetSymbolAddress((void**)&degp, g_deg);
    int* curp;    cudaGetSymbolAddress((void**)&curp, g_cursor);

    // side stream + events for fork/join inside graph capture
    cudaStream_t side;
    cudaStreamCreateWithFlags(&side, cudaStreamNonBlocking);
    cudaEvent_t evF, evJ;
    cudaEventCreateWithFlags(&evF, cudaEventDisableTiming);
    cudaEventCreateWithFlags(&evJ, cudaEventDisableTiming);

    // fork: CSR build on side stream
    cudaEventRecord(evF, 0);
    cudaStreamWaitEvent(side, evF, 0);
    cudaMemsetAsync(degp, 0, N_NODES * sizeof(int), side);
    cudaMemsetAsync(curp, 0, N_NODES * sizeof(int), side);
    hist_kernel<<<(N_EDGES + 255) / 256, 256, 0, side>>>(ei);
    scan_kernel<<<1, 1024, 0, side>>>();
    scatter_kernel<<<(N_EDGES + 255) / 256, 256, 0, side>>>(ei);
    cudaEventRecord(evJ, side);

    // main: weight converts + gemm1 (scores fused)
    f2h_kernel<<<(F_IN * C1 / 4 + 255) / 256, 256>>>(W1, w1hp, F_IN * C1);
    f2h_kernel<<<(C1 * HID / 4 + 255) / 256, 256>>>(W2, w2hp, C1 * HID);
    graph_offsets_kernel<<<1, 128>>>(bat);

    dim3 g1(C1 / 64, (N_NODES + 127) / 128);
    gemm_gat_kernel<true><<<g1, 256>>>(x, w1hp, h1p, N_NODES, C1, F_IN,
                                       as1, ad1, s1p, d1p, HEADS);

    // join: aggregate1 needs CSR + scores
    cudaStreamWaitEvent(0, evJ, 0);
    aggregate1_kernel<<<(N_NODES * 32 + 255) / 256, 256>>>(b1);

    // layer 2 (scores fused)
    dim3 g2(HID / 64, (N_NODES + 127) / 128);
    gemm_gat_kernel<false><<<g2, 256>>>(o1p, w2hp, h2p, N_NODES, HID, C1,
                                        as2, ad2, s2p, d2p, 1);
    aggregate2_kernel<<<(N_NODES * 32 + 255) / 256, 256>>>(b2);

    // pool + classifier
    pool_fc_kernel<<<NG, 256>>>(fcw, fcb, out);
}